// round 1
// baseline (speedup 1.0000x reference)
#include <cuda_runtime.h>
#include <cstdint>

#define H 128
#define W 128
#define HW 16384
#define OH 512
#define OWID 512
#define NQ (OH*OWID)

// ------------------------------ scratch (device globals, no allocation) ----
__device__ float g_h0[64*HW];
__device__ float g_A [64*HW];
__device__ float g_B [64*HW];
__device__ float g_C [64*HW];
__device__ float g_G [(size_t)HW*256];
__device__ float g_b0eff[256];

// ------------------------------ 3x3 conv, pad 1, OIHW weights --------------
#define CTX 32
#define CTY 4

__global__ void conv3x3_kernel(const float* __restrict__ in,
                               const float* __restrict__ w,
                               const float* __restrict__ bias,
                               const float* __restrict__ res,
                               float* __restrict__ out,
                               int IC, int do_relu)
{
    __shared__ float in_s[16][CTY+2][CTX+2];
    __shared__ float w_s[16*9*16];
    const int tx = threadIdx.x, ty = threadIdx.y;
    const int tid = ty*CTX + tx;
    const int x0 = blockIdx.x*CTX, y0 = blockIdx.y*CTY;
    const int ocg0 = blockIdx.z*16;

    float acc[16];
#pragma unroll
    for (int i = 0; i < 16; i++) acc[i] = 0.f;

    for (int ic0 = 0; ic0 < IC; ic0 += 16) {
        const int icb = min(16, IC - ic0);
        __syncthreads();
        const int tot = icb*(CTY+2)*(CTX+2);
        for (int i = tid; i < tot; i += CTX*CTY) {
            int ic  = i / ((CTY+2)*(CTX+2));
            int rem = i % ((CTY+2)*(CTX+2));
            int ly = rem / (CTX+2), lx = rem % (CTX+2);
            int gy = y0 - 1 + ly, gx = x0 - 1 + lx;
            float v = 0.f;
            if (gy >= 0 && gy < H && gx >= 0 && gx < W)
                v = in[(size_t)(ic0+ic)*HW + gy*W + gx];
            in_s[ic][ly][lx] = v;
        }
        const int wtot = icb*9*16;
        for (int i = tid; i < wtot; i += CTX*CTY) {
            int oc = i & 15;
            int t2 = i >> 4;
            int tap = t2 % 9, ic = t2 / 9;
            w_s[(ic*9+tap)*16 + oc] =
                w[(size_t)(ocg0+oc)*IC*9 + (size_t)(ic0+ic)*9 + tap];
        }
        __syncthreads();
        for (int ic = 0; ic < icb; ic++) {
#pragma unroll
            for (int tap = 0; tap < 9; tap++) {
                const int dy = tap/3, dx = tap%3;
                float a = in_s[ic][ty+dy][tx+dx];
                const float4* wp = (const float4*)&w_s[(ic*9+tap)*16];
                float wv[16];
                *(float4*)&wv[0]  = wp[0];
                *(float4*)&wv[4]  = wp[1];
                *(float4*)&wv[8]  = wp[2];
                *(float4*)&wv[12] = wp[3];
#pragma unroll
                for (int oc = 0; oc < 16; oc++)
                    acc[oc] = fmaf(a, wv[oc], acc[oc]);
            }
        }
    }
    const int pix = (y0+ty)*W + (x0+tx);
#pragma unroll
    for (int oc = 0; oc < 16; oc++) {
        float v = acc[oc];
        if (bias) v += bias[ocg0+oc];
        if (res)  v += res[(size_t)(ocg0+oc)*HW + pix];
        if (do_relu) v = fmaxf(v, 0.f);
        out[(size_t)(ocg0+oc)*HW + pix] = v;
    }
}

// ---- layer-0 conv: G[p][0:256] = conv3x3(feat64, mw0[0:576]) ---------------
// mw0 row index k = c*9 + (kh*3+kw), column = output neuron. Output [pixel][256].
__global__ void conv_l0_kernel(const float* __restrict__ in,
                               const float* __restrict__ mw0,
                               float* __restrict__ G)
{
    __shared__ float in_s[16][CTY+2][CTX+2];
    __shared__ float w_s[16*9*16];
    const int tx = threadIdx.x, ty = threadIdx.y;
    const int tid = ty*CTX + tx;
    const int x0 = blockIdx.x*CTX, y0 = blockIdx.y*CTY;
    const int ocg0 = blockIdx.z*16;

    float acc[16];
#pragma unroll
    for (int i = 0; i < 16; i++) acc[i] = 0.f;

    for (int ic0 = 0; ic0 < 64; ic0 += 16) {
        __syncthreads();
        const int tot = 16*(CTY+2)*(CTX+2);
        for (int i = tid; i < tot; i += CTX*CTY) {
            int ic  = i / ((CTY+2)*(CTX+2));
            int rem = i % ((CTY+2)*(CTX+2));
            int ly = rem / (CTX+2), lx = rem % (CTX+2);
            int gy = y0 - 1 + ly, gx = x0 - 1 + lx;
            float v = 0.f;
            if (gy >= 0 && gy < H && gx >= 0 && gx < W)
                v = in[(size_t)(ic0+ic)*HW + gy*W + gx];
            in_s[ic][ly][lx] = v;
        }
        for (int i = tid; i < 16*9*16; i += CTX*CTY) {
            int oc = i & 15;
            int t2 = i >> 4;
            int tap = t2 % 9, ic = t2 / 9;
            w_s[(ic*9+tap)*16 + oc] =
                mw0[(size_t)((ic0+ic)*9 + tap)*256 + ocg0 + oc];
        }
        __syncthreads();
        for (int ic = 0; ic < 16; ic++) {
#pragma unroll
            for (int tap = 0; tap < 9; tap++) {
                const int dy = tap/3, dx = tap%3;
                float a = in_s[ic][ty+dy][tx+dx];
                const float4* wp = (const float4*)&w_s[(ic*9+tap)*16];
                float wv[16];
                *(float4*)&wv[0]  = wp[0];
                *(float4*)&wv[4]  = wp[1];
                *(float4*)&wv[8]  = wp[2];
                *(float4*)&wv[12] = wp[3];
#pragma unroll
                for (int oc = 0; oc < 16; oc++)
                    acc[oc] = fmaf(a, wv[oc], acc[oc]);
            }
        }
    }
    const int pix = (y0+ty)*W + (x0+tx);
#pragma unroll
    for (int oc = 0; oc < 16; oc++)
        G[(size_t)pix*256 + ocg0 + oc] = acc[oc];
}

// ---- fold q_cell (constant [0.5,0.5]) into layer-0 bias --------------------
__global__ void prep_kernel(const float* __restrict__ mw0,
                            const float* __restrict__ mb0,
                            float* __restrict__ b0eff)
{
    int o = threadIdx.x;
    b0eff[o] = mb0[o] + 0.5f*mw0[578*256 + o] + 0.5f*mw0[579*256 + o];
}

// ------------------------------ LIIF query + MLP ----------------------------
#define QB 32          // queries per block
#define SB 128         // samples per block (QB*4)
#define AS 257         // act row stride (conflict-free)
#define QTHREADS 512
#define QSMEM_BYTES ((SB*AS + 64*256)*4)

__global__ __launch_bounds__(QTHREADS, 1)
void query_kernel(const float* __restrict__ G,
                  const float* __restrict__ mw0,
                  const float* __restrict__ b0eff,
                  const float* __restrict__ w1, const float* __restrict__ b1,
                  const float* __restrict__ w2, const float* __restrict__ b2,
                  const float* __restrict__ w3, const float* __restrict__ b3,
                  const float* __restrict__ w4, const float* __restrict__ b4,
                  float* __restrict__ out)
{
    extern __shared__ float dyn[];
    float* act = dyn;              // [SB][AS]
    float* wsm = dyn + SB*AS;      // [64][256]
    __shared__ int   p_s[SB];
    __shared__ float relh_s[SB], relw_s[SB], area_s[SB];
    __shared__ float pred_s[SB][4];

    const int tid = threadIdx.x;

    // ---- stage 0: per-sample geometry (exactly mirrors the fp32 reference)
    if (tid < SB) {
        int m  = tid;
        int q  = blockIdx.x*QB + (m >> 2);
        int oh = q >> 9, ow = q & 511;
        int r  = (m >> 1) & 1, c = m & 1;
        float sh = (oh + 0.5f)*(2.0f/512.0f) - 1.0f;
        float sw = (ow + 0.5f)*(2.0f/512.0f) - 1.0f;
        const float d = 1.0f/128.0f, EPS = 1e-6f;
        float gh = fminf(fmaxf(sh + (2.f*r - 1.f)*d, -1.f + EPS), 1.f - EPS);
        float gw = fminf(fmaxf(sw + (2.f*c - 1.f)*d, -1.f + EPS), 1.f - EPS);
        float fy = ((gh + 1.0f)*128.0f - 1.0f)*0.5f;
        float fx = ((gw + 1.0f)*128.0f - 1.0f)*0.5f;
        int iy = min(max((int)rintf(fy), 0), 127);   // round half-to-even
        int ix = min(max((int)rintf(fx), 0), 127);
        float qgh = (iy + 0.5f)*(2.0f/128.0f) - 1.0f;
        float qgw = (ix + 0.5f)*(2.0f/128.0f) - 1.0f;
        float rh = (sh - qgh)*128.0f;
        float rw = (sw - qgw)*128.0f;
        p_s[m] = iy*128 + ix;
        relh_s[m] = rh; relw_s[m] = rw;
        area_s[m] = fabsf(rh*rw);
    }
    __syncthreads();

    // ---- stage 1: h1 = relu(G[p] + rel_h*U + rel_w*V + b0eff)
    {
        int oc = tid & 255;
        float u = mw0[576*256 + oc];
        float v = mw0[577*256 + oc];
        float b = b0eff[oc];
        for (int m = (tid >> 8); m < SB; m += 2) {
            float g = G[(size_t)p_s[m]*256 + oc];
            float val = fmaf(relh_s[m], u, fmaf(relw_s[m], v, g + b));
            act[m*AS + oc] = fmaxf(val, 0.f);
        }
    }

    // ---- stage 2: 3 hidden layers 256->256 (+relu), register-tiled 8x8
    const int lane = tid & 31, warp = tid >> 5;
    const int o0 = lane*8, m0 = warp*8;
    for (int L = 0; L < 3; L++) {
        const float* Wl = (L == 0) ? w1 : (L == 1) ? w2 : w3;
        const float* Bl = (L == 0) ? b1 : (L == 1) ? b2 : b3;
        float acc[8][8];
#pragma unroll
        for (int j = 0; j < 8; j++)
#pragma unroll
            for (int i = 0; i < 8; i++) acc[j][i] = 0.f;

        for (int kc = 0; kc < 4; kc++) {
            __syncthreads();
            const float4* W4 = (const float4*)(Wl + (size_t)kc*16384);
            float4* wsm4 = (float4*)wsm;
            for (int i = tid; i < 4096; i += QTHREADS) wsm4[i] = W4[i];
            __syncthreads();
#pragma unroll 2
            for (int kk = 0; kk < 64; kk++) {
                const float4* wp = (const float4*)&wsm[kk*256 + o0];
                float4 wa = wp[0], wb = wp[1];
                int kb = kc*64 + kk;
#pragma unroll
                for (int j = 0; j < 8; j++) {
                    float a = act[(m0 + j)*AS + kb];
                    acc[j][0] = fmaf(a, wa.x, acc[j][0]);
                    acc[j][1] = fmaf(a, wa.y, acc[j][1]);
                    acc[j][2] = fmaf(a, wa.z, acc[j][2]);
                    acc[j][3] = fmaf(a, wa.w, acc[j][3]);
                    acc[j][4] = fmaf(a, wb.x, acc[j][4]);
                    acc[j][5] = fmaf(a, wb.y, acc[j][5]);
                    acc[j][6] = fmaf(a, wb.z, acc[j][6]);
                    acc[j][7] = fmaf(a, wb.w, acc[j][7]);
                }
            }
        }
        float bv[8];
#pragma unroll
        for (int i = 0; i < 8; i++) bv[i] = Bl[o0 + i];
        __syncthreads();
#pragma unroll
        for (int j = 0; j < 8; j++)
#pragma unroll
            for (int i = 0; i < 8; i++)
                act[(m0 + j)*AS + o0 + i] = fmaxf(acc[j][i] + bv[i], 0.f);
        __syncthreads();
    }

    // ---- stage 3: output layer 256->3
    for (int i = tid; i < 768; i += QTHREADS) wsm[i] = w4[i];
    __syncthreads();
    if (tid < SB) {
        int m = tid;
        float s0 = b4[0], s1 = b4[1], s2 = b4[2];
        for (int k = 0; k < 256; k++) {
            float a = act[m*AS + k];
            s0 = fmaf(a, wsm[k*3 + 0], s0);
            s1 = fmaf(a, wsm[k*3 + 1], s1);
            s2 = fmaf(a, wsm[k*3 + 2], s2);
        }
        pred_s[m][0] = s0; pred_s[m][1] = s1; pred_s[m][2] = s2;
    }
    __syncthreads();

    // ---- stage 4: LIIF ensemble (diagonal area weights) + clip
    if (tid < QB) {
        int base = tid*4;
        float a0 = area_s[base+0], a1 = area_s[base+1];
        float a2 = area_s[base+2], a3 = area_s[base+3];
        float tot = a0 + a1 + a2 + a3 + 1e-9f;
        int q = blockIdx.x*QB + tid;
#pragma unroll
        for (int j = 0; j < 3; j++) {
            float num = pred_s[base+0][j]*a3 + pred_s[base+1][j]*a2
                      + pred_s[base+2][j]*a1 + pred_s[base+3][j]*a0;
            float yv = num / tot;
            yv = fminf(fmaxf(yv, 0.f), 1.f);
            out[(size_t)j*NQ + q] = yv;
        }
    }
}

// ------------------------------ launch --------------------------------------
extern "C" void kernel_launch(void* const* d_in, const int* in_sizes, int n_in,
                              void* d_out, int out_size)
{
    const float* x      = (const float*)d_in[0];
    const float* head_w = (const float*)d_in[2];
    const float* head_b = (const float*)d_in[3];
    const float* rb_w   = (const float*)d_in[4];
    const float* rb_b   = (const float*)d_in[5];
    const float* tail_w = (const float*)d_in[6];
    const float* tail_b = (const float*)d_in[7];
    const float* mw0 = (const float*)d_in[8];
    const float* mb0 = (const float*)d_in[9];
    const float* mw1 = (const float*)d_in[10];
    const float* mb1 = (const float*)d_in[11];
    const float* mw2 = (const float*)d_in[12];
    const float* mb2 = (const float*)d_in[13];
    const float* mw3 = (const float*)d_in[14];
    const float* mb3 = (const float*)d_in[15];
    const float* mw4 = (const float*)d_in[16];
    const float* mb4 = (const float*)d_in[17];
    float* out = (float*)d_out;

    float *h0, *A, *B, *C, *G, *b0eff;
    cudaGetSymbolAddress((void**)&h0, g_h0);
    cudaGetSymbolAddress((void**)&A,  g_A);
    cudaGetSymbolAddress((void**)&B,  g_B);
    cudaGetSymbolAddress((void**)&C,  g_C);
    cudaGetSymbolAddress((void**)&G,  g_G);
    cudaGetSymbolAddress((void**)&b0eff, g_b0eff);

    dim3 cb(CTX, CTY);
    dim3 cg(W/CTX, H/CTY, 4);      // 64 output channels

    // EDSR encoder
    conv3x3_kernel<<<cg, cb>>>(x, head_w, head_b, nullptr, h0, 3, 0);
    const float* hcur = h0;
    float* pp[2] = {A, C};
    for (int i = 0; i < 16; i++) {
        conv3x3_kernel<<<cg, cb>>>(hcur, rb_w + (size_t)(2*i)*36864,
                                   rb_b + 2*i*64, nullptr, B, 64, 1);
        float* ho = pp[i & 1];
        conv3x3_kernel<<<cg, cb>>>(B, rb_w + (size_t)(2*i+1)*36864,
                                   rb_b + (2*i+1)*64, hcur, ho, 64, 0);
        hcur = ho;
    }
    conv3x3_kernel<<<cg, cb>>>(hcur, tail_w, tail_b, h0, B, 64, 0); // feat in B

    // layer-0-as-conv: G[16384][256]
    dim3 lg(W/CTX, H/CTY, 16);
    conv_l0_kernel<<<lg, cb>>>(B, mw0, G);

    prep_kernel<<<1, 256>>>(mw0, mb0, b0eff);

    cudaFuncSetAttribute(query_kernel,
                         cudaFuncAttributeMaxDynamicSharedMemorySize,
                         QSMEM_BYTES);
    query_kernel<<<NQ/QB, QTHREADS, QSMEM_BYTES>>>(
        G, mw0, b0eff, mw1, mb1, mw2, mb2, mw3, mb3, mw4, mb4, out);
}

// round 3
// speedup vs baseline: 1.9985x; 1.9985x over previous
#include <cuda_runtime.h>
#include <cstdint>

#define H 128
#define W 128
#define HW 16384
#define OH 512
#define OWID 512
#define NQ (OH*OWID)

// ------------------------------ scratch (device globals, no allocation) ----
__device__ float g_h0[64*HW];
__device__ float g_A [64*HW];
__device__ float g_B [64*HW];
__device__ float g_C [64*HW];
__device__ float g_G [(size_t)HW*256];
__device__ float g_b0eff[256];
__device__ uint32_t g_w1t[65536];   // tf32-rounded, [K][N] (original layout)
__device__ uint32_t g_w2t[65536];
__device__ uint32_t g_w3t[65536];

// ------------------------------ PTX helpers --------------------------------
__device__ __forceinline__ uint32_t smem_u32(const void* p) {
    uint32_t a;
    asm("{ .reg .u64 t; cvta.to.shared.u64 t, %1; cvt.u32.u64 %0, t; }"
        : "=r"(a) : "l"(p));
    return a;
}
__device__ __forceinline__ uint32_t f2tf32(float x) {
    uint32_t r; asm("cvt.rna.tf32.f32 %0, %1;" : "=r"(r) : "f"(x)); return r;
}
__device__ __forceinline__ void cp_async16(uint32_t dst, const void* src) {
    asm volatile("cp.async.ca.shared.global [%0], [%1], 16;"
                 :: "r"(dst), "l"(src) : "memory");
}
__device__ __forceinline__ void cp_commit() {
    asm volatile("cp.async.commit_group;" ::: "memory");
}
template<int N> __device__ __forceinline__ void cp_wait() {
    asm volatile("cp.async.wait_group %0;" :: "n"(N) : "memory");
}
// m16n8k8 tf32 MMA, A row-major, B col-major, f32 accumulate (in-place)
__device__ __forceinline__ void mma8(float* d,
                                     uint32_t a0, uint32_t a1, uint32_t a2, uint32_t a3,
                                     uint32_t b0, uint32_t b1) {
    asm volatile(
        "mma.sync.aligned.m16n8k8.row.col.f32.tf32.tf32.f32 "
        "{%0,%1,%2,%3},{%4,%5,%6,%7},{%8,%9},{%0,%1,%2,%3};"
        : "+f"(d[0]), "+f"(d[1]), "+f"(d[2]), "+f"(d[3])
        : "r"(a0), "r"(a1), "r"(a2), "r"(a3), "r"(b0), "r"(b1));
}

// ------------------------------ 3x3 conv, pad 1, OIHW weights --------------
#define CTX 32
#define CTY 4

__global__ void conv3x3_kernel(const float* __restrict__ in,
                               const float* __restrict__ w,
                               const float* __restrict__ bias,
                               const float* __restrict__ res,
                               float* __restrict__ out,
                               int IC, int do_relu)
{
    __shared__ float in_s[16][CTY+2][CTX+2];
    __shared__ float w_s[16*9*16];
    const int tx = threadIdx.x, ty = threadIdx.y;
    const int tid = ty*CTX + tx;
    const int x0 = blockIdx.x*CTX, y0 = blockIdx.y*CTY;
    const int ocg0 = blockIdx.z*16;

    float acc[16];
#pragma unroll
    for (int i = 0; i < 16; i++) acc[i] = 0.f;

    for (int ic0 = 0; ic0 < IC; ic0 += 16) {
        const int icb = min(16, IC - ic0);
        __syncthreads();
        const int tot = icb*(CTY+2)*(CTX+2);
        for (int i = tid; i < tot; i += CTX*CTY) {
            int ic  = i / ((CTY+2)*(CTX+2));
            int rem = i % ((CTY+2)*(CTX+2));
            int ly = rem / (CTX+2), lx = rem % (CTX+2);
            int gy = y0 - 1 + ly, gx = x0 - 1 + lx;
            float v = 0.f;
            if (gy >= 0 && gy < H && gx >= 0 && gx < W)
                v = in[(size_t)(ic0+ic)*HW + gy*W + gx];
            in_s[ic][ly][lx] = v;
        }
        const int wtot = icb*9*16;
        for (int i = tid; i < wtot; i += CTX*CTY) {
            int oc = i & 15;
            int t2 = i >> 4;
            int tap = t2 % 9, ic = t2 / 9;
            w_s[(ic*9+tap)*16 + oc] =
                w[(size_t)(ocg0+oc)*IC*9 + (size_t)(ic0+ic)*9 + tap];
        }
        __syncthreads();
        for (int ic = 0; ic < icb; ic++) {
#pragma unroll
            for (int tap = 0; tap < 9; tap++) {
                const int dy = tap/3, dx = tap%3;
                float a = in_s[ic][ty+dy][tx+dx];
                const float4* wp = (const float4*)&w_s[(ic*9+tap)*16];
                float wv[16];
                *(float4*)&wv[0]  = wp[0];
                *(float4*)&wv[4]  = wp[1];
                *(float4*)&wv[8]  = wp[2];
                *(float4*)&wv[12] = wp[3];
#pragma unroll
                for (int oc = 0; oc < 16; oc++)
                    acc[oc] = fmaf(a, wv[oc], acc[oc]);
            }
        }
    }
    const int pix = (y0+ty)*W + (x0+tx);
#pragma unroll
    for (int oc = 0; oc < 16; oc++) {
        float v = acc[oc];
        if (bias) v += bias[ocg0+oc];
        if (res)  v += res[(size_t)(ocg0+oc)*HW + pix];
        if (do_relu) v = fmaxf(v, 0.f);
        out[(size_t)(ocg0+oc)*HW + pix] = v;
    }
}

// ---- layer-0 conv: G[p][0:256] = conv3x3(feat64, mw0[0:576]) ---------------
__global__ void conv_l0_kernel(const float* __restrict__ in,
                               const float* __restrict__ mw0,
                               float* __restrict__ G)
{
    __shared__ float in_s[16][CTY+2][CTX+2];
    __shared__ float w_s[16*9*16];
    const int tx = threadIdx.x, ty = threadIdx.y;
    const int tid = ty*CTX + tx;
    const int x0 = blockIdx.x*CTX, y0 = blockIdx.y*CTY;
    const int ocg0 = blockIdx.z*16;

    float acc[16];
#pragma unroll
    for (int i = 0; i < 16; i++) acc[i] = 0.f;

    for (int ic0 = 0; ic0 < 64; ic0 += 16) {
        __syncthreads();
        const int tot = 16*(CTY+2)*(CTX+2);
        for (int i = tid; i < tot; i += CTX*CTY) {
            int ic  = i / ((CTY+2)*(CTX+2));
            int rem = i % ((CTY+2)*(CTX+2));
            int ly = rem / (CTX+2), lx = rem % (CTX+2);
            int gy = y0 - 1 + ly, gx = x0 - 1 + lx;
            float v = 0.f;
            if (gy >= 0 && gy < H && gx >= 0 && gx < W)
                v = in[(size_t)(ic0+ic)*HW + gy*W + gx];
            in_s[ic][ly][lx] = v;
        }
        for (int i = tid; i < 16*9*16; i += CTX*CTY) {
            int oc = i & 15;
            int t2 = i >> 4;
            int tap = t2 % 9, ic = t2 / 9;
            w_s[(ic*9+tap)*16 + oc] =
                mw0[(size_t)((ic0+ic)*9 + tap)*256 + ocg0 + oc];
        }
        __syncthreads();
        for (int ic = 0; ic < 16; ic++) {
#pragma unroll
            for (int tap = 0; tap < 9; tap++) {
                const int dy = tap/3, dx = tap%3;
                float a = in_s[ic][ty+dy][tx+dx];
                const float4* wp = (const float4*)&w_s[(ic*9+tap)*16];
                float wv[16];
                *(float4*)&wv[0]  = wp[0];
                *(float4*)&wv[4]  = wp[1];
                *(float4*)&wv[8]  = wp[2];
                *(float4*)&wv[12] = wp[3];
#pragma unroll
                for (int oc = 0; oc < 16; oc++)
                    acc[oc] = fmaf(a, wv[oc], acc[oc]);
            }
        }
    }
    const int pix = (y0+ty)*W + (x0+tx);
#pragma unroll
    for (int oc = 0; oc < 16; oc++)
        G[(size_t)pix*256 + ocg0 + oc] = acc[oc];
}

// ---- prep: fold q_cell into bias ------------------------------------------
__global__ void prep_kernel(const float* __restrict__ mw0,
                            const float* __restrict__ mb0,
                            float* __restrict__ b0eff)
{
    int o = threadIdx.x;
    b0eff[o] = mb0[o] + 0.5f*mw0[578*256 + o] + 0.5f*mw0[579*256 + o];
}

// ---- round weights to tf32 (round-to-nearest), keep [K][N] layout ----------
__global__ void round_tf32_kernel(const float* __restrict__ w,
                                  uint32_t* __restrict__ wt)
{
    int idx = blockIdx.x*256 + threadIdx.x;
    wt[idx] = f2tf32(w[idx]);
}

// ------------------------------ LIIF query + mma.sync tf32 MLP --------------
#define QB 32
#define SB 128
#define QTHREADS 256
#define AS 264                       // act row stride (words) - conflict-free frags
#define OFF_ACT 0
#define OFF_WB0 (SB*AS)              // 33792
#define OFF_WB1 (OFF_WB0 + 32*AS)    // 42240
#define OFF_BIAS (OFF_WB1 + 32*AS)   // 50688
#define DYN_FLOATS (OFF_BIAS + 256)  // 50944
#define DYN_BYTES (DYN_FLOATS*4)     // 203776

__device__ __forceinline__ void load_wchunk(uint32_t dst_base,
                                            const uint32_t* __restrict__ Wg,
                                            int c, int tid)
{
#pragma unroll
    for (int ii = 0; ii < 8; ii++) {
        int i = tid + ii*QTHREADS;
        int r = i >> 6, q = i & 63;
        cp_async16(dst_base + (uint32_t)(r*AS + q*4)*4u,
                   Wg + (size_t)(c*32 + r)*256 + q*4);
    }
}

__global__ __launch_bounds__(QTHREADS)
void query_kernel(const float* __restrict__ G,
                  const float* __restrict__ mw0,
                  const float* __restrict__ b0eff,
                  const uint32_t* __restrict__ w1t, const float* __restrict__ b1,
                  const uint32_t* __restrict__ w2t, const float* __restrict__ b2,
                  const uint32_t* __restrict__ w3t, const float* __restrict__ b3,
                  const float* __restrict__ w4, const float* __restrict__ b4,
                  float* __restrict__ out)
{
    extern __shared__ float dyn[];
    float*    act  = dyn + OFF_ACT;
    uint32_t* actu = (uint32_t*)act;
    float*    bias_s = dyn + OFF_BIAS;
    __shared__ int   p_s[SB];
    __shared__ float relh_s[SB], relw_s[SB], area_s[SB];
    __shared__ float pred_s[SB][4];

    const int tid  = threadIdx.x;
    const int wid  = tid >> 5;
    const int lane = tid & 31;
    const int g    = lane >> 2;     // 0..7
    const int t    = lane & 3;      // 0..3

    const uint32_t dynaddr = smem_u32(dyn);
    const uint32_t wbaddr[2] = {dynaddr + OFF_WB0*4u, dynaddr + OFF_WB1*4u};
    const uint32_t* wbuf[2] = {(const uint32_t*)(dyn + OFF_WB0),
                               (const uint32_t*)(dyn + OFF_WB1)};

    // ---- stage 0: per-sample geometry (mirrors fp32 reference exactly)
    if (tid < SB) {
        int m  = tid;
        int q  = blockIdx.x*QB + (m >> 2);
        int oh = q >> 9, ow = q & 511;
        int r  = (m >> 1) & 1, c = m & 1;
        float sh = (oh + 0.5f)*(2.0f/512.0f) - 1.0f;
        float sw = (ow + 0.5f)*(2.0f/512.0f) - 1.0f;
        const float d = 1.0f/128.0f, EPS = 1e-6f;
        float gh = fminf(fmaxf(sh + (2.f*r - 1.f)*d, -1.f + EPS), 1.f - EPS);
        float gw = fminf(fmaxf(sw + (2.f*c - 1.f)*d, -1.f + EPS), 1.f - EPS);
        float fy = ((gh + 1.0f)*128.0f - 1.0f)*0.5f;
        float fx = ((gw + 1.0f)*128.0f - 1.0f)*0.5f;
        int iy = min(max((int)rintf(fy), 0), 127);
        int ix = min(max((int)rintf(fx), 0), 127);
        float qgh = (iy + 0.5f)*(2.0f/128.0f) - 1.0f;
        float qgw = (ix + 0.5f)*(2.0f/128.0f) - 1.0f;
        float rh = (sh - qgh)*128.0f;
        float rw = (sw - qgw)*128.0f;
        p_s[m] = iy*128 + ix;
        relh_s[m] = rh; relw_s[m] = rw;
        area_s[m] = fabsf(rh*rw);
    }

    // start prefetch of layer-1 weight chunk 0 ASAP (before stage 1)
    load_wchunk(wbaddr[0], w1t, 0, tid);
    cp_commit();
    __syncthreads();

    // ---- stage 1: A0 = relu(G[p] + rel_h*U + rel_w*V + b0eff) -> tf32
    {
        int oc = tid;               // 256 threads = 256 output neurons
        float u = mw0[576*256 + oc];
        float v = mw0[577*256 + oc];
        float b = b0eff[oc];
#pragma unroll 4
        for (int m = 0; m < SB; m++) {
            float gg = G[(size_t)p_s[m]*256 + oc];
            float val = fmaf(relh_s[m], u, fmaf(relw_s[m], v, gg + b));
            actu[m*AS + oc] = f2tf32(fmaxf(val, 0.f));
        }
    }
    __syncthreads();

    // ---- stage 2: 3 hidden layers, warp-level tf32 MMA
    const int m0 = (wid & 3)*32;     // warp M origin
    const int n0b = (wid >> 2)*128;  // warp N origin

    const uint32_t* Ws[3] = {w1t, w2t, w3t};
    const float*    Bs[3] = {b1, b2, b3};

    int cnt = 0;   // global chunk counter; parity selects buffer
    for (int L = 0; L < 3; L++) {
        bias_s[tid] = Bs[L][tid];

        float acc[2][16][4];
#pragma unroll
        for (int mt = 0; mt < 2; mt++)
#pragma unroll
            for (int nt = 0; nt < 16; nt++)
#pragma unroll
                for (int i = 0; i < 4; i++) acc[mt][nt][i] = 0.f;

        for (int c = 0; c < 8; c++) {
            const bool has_next = (c < 7) || (L < 2);
            if (has_next) {
                const uint32_t* Wn = (c < 7) ? Ws[L] : Ws[L+1];
                const int cn = (c < 7) ? c + 1 : 0;
                load_wchunk(wbaddr[(cnt + 1) & 1], Wn, cn, tid);
                cp_commit();
                cp_wait<1>();
            } else {
                cp_wait<0>();
            }
            __syncthreads();

            const uint32_t* wb = wbuf[cnt & 1];
#pragma unroll
            for (int ks = 0; ks < 4; ks++) {
                const int kabs = c*32 + ks*8;
                uint32_t af[2][4];
#pragma unroll
                for (int mt = 0; mt < 2; mt++) {
                    const uint32_t* ar = actu + (m0 + mt*16 + g)*AS + kabs + t;
                    af[mt][0] = ar[0];
                    af[mt][2] = ar[4];
                    af[mt][1] = ar[8*AS];
                    af[mt][3] = ar[8*AS + 4];
                }
                const uint32_t* wp = wb + (ks*8 + t)*AS + n0b + g;
#pragma unroll
                for (int nt = 0; nt < 16; nt++) {
                    uint32_t b0 = wp[nt*8];
                    uint32_t b1r = wp[4*AS + nt*8];
                    mma8(acc[0][nt], af[0][0], af[0][1], af[0][2], af[0][3], b0, b1r);
                    mma8(acc[1][nt], af[1][0], af[1][1], af[1][2], af[1][3], b0, b1r);
                }
            }
            cnt++;
            __syncthreads();
        }

        // ---- epilogue: acc + bias -> relu -> act (tf32 except last layer)
        const bool lastL = (L == 2);
#pragma unroll
        for (int mt = 0; mt < 2; mt++) {
            const int r0 = m0 + mt*16 + g;
#pragma unroll
            for (int nt = 0; nt < 16; nt++) {
                const int col = n0b + nt*8 + 2*t;
                float v0 = fmaxf(acc[mt][nt][0] + bias_s[col],     0.f);
                float v1 = fmaxf(acc[mt][nt][1] + bias_s[col + 1], 0.f);
                float v2 = fmaxf(acc[mt][nt][2] + bias_s[col],     0.f);
                float v3 = fmaxf(acc[mt][nt][3] + bias_s[col + 1], 0.f);
                if (!lastL) {
                    actu[r0*AS + col]       = f2tf32(v0);
                    actu[r0*AS + col + 1]   = f2tf32(v1);
                    actu[(r0+8)*AS + col]   = f2tf32(v2);
                    actu[(r0+8)*AS + col+1] = f2tf32(v3);
                } else {
                    act[r0*AS + col]        = v0;
                    act[r0*AS + col + 1]    = v1;
                    act[(r0+8)*AS + col]    = v2;
                    act[(r0+8)*AS + col+1]  = v3;
                }
            }
        }
        __syncthreads();
    }

    // ---- stage 3: output layer 256->3 (fp32)
    {
        float* wsm = dyn + OFF_WB0;          // weight buffers are free now
        for (int i = tid; i < 768; i += QTHREADS) wsm[i] = w4[i];
        __syncthreads();
        if (tid < SB) {
            const float* ap = act + tid*AS;
            float s0 = b4[0], s1 = b4[1], s2 = b4[2];
#pragma unroll 4
            for (int k = 0; k < 256; k++) {
                float a = ap[k];
                s0 = fmaf(a, wsm[k*3 + 0], s0);
                s1 = fmaf(a, wsm[k*3 + 1], s1);
                s2 = fmaf(a, wsm[k*3 + 2], s2);
            }
            pred_s[tid][0] = s0; pred_s[tid][1] = s1; pred_s[tid][2] = s2;
        }
    }
    __syncthreads();

    // ---- stage 4: LIIF ensemble (diagonal areas) + clip
    if (tid < QB) {
        int bb = tid*4;
        float a0 = area_s[bb+0], a1 = area_s[bb+1];
        float a2 = area_s[bb+2], a3 = area_s[bb+3];
        float tot = a0 + a1 + a2 + a3 + 1e-9f;
        int q = blockIdx.x*QB + tid;
#pragma unroll
        for (int j = 0; j < 3; j++) {
            float num = pred_s[bb+0][j]*a3 + pred_s[bb+1][j]*a2
                      + pred_s[bb+2][j]*a1 + pred_s[bb+3][j]*a0;
            float yv = num / tot;
            yv = fminf(fmaxf(yv, 0.f), 1.f);
            out[(size_t)j*NQ + q] = yv;
        }
    }
}

// ------------------------------ launch --------------------------------------
extern "C" void kernel_launch(void* const* d_in, const int* in_sizes, int n_in,
                              void* d_out, int out_size)
{
    const float* x      = (const float*)d_in[0];
    const float* head_w = (const float*)d_in[2];
    const float* head_b = (const float*)d_in[3];
    const float* rb_w   = (const float*)d_in[4];
    const float* rb_b   = (const float*)d_in[5];
    const float* tail_w = (const float*)d_in[6];
    const float* tail_b = (const float*)d_in[7];
    const float* mw0 = (const float*)d_in[8];
    const float* mb0 = (const float*)d_in[9];
    const float* mw1 = (const float*)d_in[10];
    const float* mb1 = (const float*)d_in[11];
    const float* mw2 = (const float*)d_in[12];
    const float* mb2 = (const float*)d_in[13];
    const float* mw3 = (const float*)d_in[14];
    const float* mb3 = (const float*)d_in[15];
    const float* mw4 = (const float*)d_in[16];
    const float* mb4 = (const float*)d_in[17];
    float* out = (float*)d_out;

    float *h0, *A, *B, *C, *G, *b0eff;
    uint32_t *w1t, *w2t, *w3t;
    cudaGetSymbolAddress((void**)&h0, g_h0);
    cudaGetSymbolAddress((void**)&A,  g_A);
    cudaGetSymbolAddress((void**)&B,  g_B);
    cudaGetSymbolAddress((void**)&C,  g_C);
    cudaGetSymbolAddress((void**)&G,  g_G);
    cudaGetSymbolAddress((void**)&b0eff, g_b0eff);
    cudaGetSymbolAddress((void**)&w1t, g_w1t);
    cudaGetSymbolAddress((void**)&w2t, g_w2t);
    cudaGetSymbolAddress((void**)&w3t, g_w3t);

    dim3 cb(CTX, CTY);
    dim3 cg(W/CTX, H/CTY, 4);

    // EDSR encoder
    conv3x3_kernel<<<cg, cb>>>(x, head_w, head_b, nullptr, h0, 3, 0);
    const float* hcur = h0;
    float* pp[2] = {A, C};
    for (int i = 0; i < 16; i++) {
        conv3x3_kernel<<<cg, cb>>>(hcur, rb_w + (size_t)(2*i)*36864,
                                   rb_b + 2*i*64, nullptr, B, 64, 1);
        float* ho = pp[i & 1];
        conv3x3_kernel<<<cg, cb>>>(B, rb_w + (size_t)(2*i+1)*36864,
                                   rb_b + (2*i+1)*64, hcur, ho, 64, 0);
        hcur = ho;
    }
    conv3x3_kernel<<<cg, cb>>>(hcur, tail_w, tail_b, h0, B, 64, 0); // feat in B

    // layer-0-as-conv: G[16384][256]
    dim3 lg(W/CTX, H/CTY, 16);
    conv_l0_kernel<<<lg, cb>>>(B, mw0, G);

    prep_kernel<<<1, 256>>>(mw0, mb0, b0eff);

    // tf32-round hidden-layer weights (layout unchanged [K][N])
    round_tf32_kernel<<<256, 256>>>(mw1, w1t);
    round_tf32_kernel<<<256, 256>>>(mw2, w2t);
    round_tf32_kernel<<<256, 256>>>(mw3, w3t);

    cudaFuncSetAttribute(query_kernel,
                         cudaFuncAttributeMaxDynamicSharedMemorySize,
                         DYN_BYTES);
    query_kernel<<<NQ/QB, QTHREADS, DYN_BYTES>>>(
        G, mw0, b0eff, w1t, mb1, w2t, mb2, w3t, mb3, mw4, mb4, out);
}

// round 4
// speedup vs baseline: 2.4858x; 1.2439x over previous
#include <cuda_runtime.h>
#include <cuda_fp16.h>
#include <cstdint>

#define H 128
#define W 128
#define HW 16384
#define OH 512
#define OWID 512
#define NQ (OH*OWID)

// ------------------------------ scratch (device globals, no allocation) ----
__device__ float g_h0[64*HW];
__device__ float g_A [64*HW];
__device__ float g_B [64*HW];
__device__ float g_C [64*HW];
__device__ __half g_G [(size_t)HW*256];
__device__ float g_b0eff[256];
__device__ __half g_w1h[65536];   // fp16, [N][K]
__device__ __half g_w2h[65536];
__device__ __half g_w3h[65536];

// ------------------------------ PTX helpers --------------------------------
__device__ __forceinline__ uint32_t smem_u32(const void* p) {
    uint32_t a;
    asm("{ .reg .u64 t; cvta.to.shared.u64 t, %1; cvt.u32.u64 %0, t; }"
        : "=r"(a) : "l"(p));
    return a;
}
__device__ __forceinline__ void cp_async16(uint32_t dst, const void* src) {
    asm volatile("cp.async.ca.shared.global [%0], [%1], 16;"
                 :: "r"(dst), "l"(src) : "memory");
}
__device__ __forceinline__ void cp_commit() {
    asm volatile("cp.async.commit_group;" ::: "memory");
}
template<int N> __device__ __forceinline__ void cp_wait() {
    asm volatile("cp.async.wait_group %0;" :: "n"(N) : "memory");
}
// m16n8k16 f16 MMA, A row-major, B col-major, f32 accumulate (in-place)
__device__ __forceinline__ void mma16(float* d,
                                      uint32_t a0, uint32_t a1, uint32_t a2, uint32_t a3,
                                      uint32_t b0, uint32_t b1) {
    asm volatile(
        "mma.sync.aligned.m16n8k16.row.col.f32.f16.f16.f32 "
        "{%0,%1,%2,%3},{%4,%5,%6,%7},{%8,%9},{%0,%1,%2,%3};"
        : "+f"(d[0]), "+f"(d[1]), "+f"(d[2]), "+f"(d[3])
        : "r"(a0), "r"(a1), "r"(a2), "r"(a3), "r"(b0), "r"(b1));
}

// ------------------------------ 3x3 conv, pad 1, OIHW weights --------------
// Block: 32x4 threads; each thread computes 2 pixels (rows ty, ty+4) x 16 oc.
#define CTX 32
#define CTY 4
#define TILEY 8

__global__ void conv3x3_kernel(const float* __restrict__ in,
                               const float* __restrict__ w,
                               const float* __restrict__ bias,
                               const float* __restrict__ res,
                               float* __restrict__ out,
                               int IC, int do_relu)
{
    __shared__ float in_s[16][TILEY+2][CTX+2];
    __shared__ float w_s[16*9*16];
    const int tx = threadIdx.x, ty = threadIdx.y;
    const int tid = ty*CTX + tx;
    const int x0 = blockIdx.x*CTX, y0 = blockIdx.y*TILEY;
    const int ocg0 = blockIdx.z*16;

    float acc0[16], acc1[16];
#pragma unroll
    for (int i = 0; i < 16; i++) { acc0[i] = 0.f; acc1[i] = 0.f; }

    for (int ic0 = 0; ic0 < IC; ic0 += 16) {
        const int icb = min(16, IC - ic0);
        __syncthreads();
        const int tot = icb*(TILEY+2)*(CTX+2);
        for (int i = tid; i < tot; i += CTX*CTY) {
            int ic  = i / ((TILEY+2)*(CTX+2));
            int rem = i % ((TILEY+2)*(CTX+2));
            int ly = rem / (CTX+2), lx = rem % (CTX+2);
            int gy = y0 - 1 + ly, gx = x0 - 1 + lx;
            float v = 0.f;
            if (gy >= 0 && gy < H && gx >= 0 && gx < W)
                v = in[(size_t)(ic0+ic)*HW + gy*W + gx];
            in_s[ic][ly][lx] = v;
        }
        const int wtot = icb*9*16;
        for (int i = tid; i < wtot; i += CTX*CTY) {
            int oc = i & 15;
            int t2 = i >> 4;
            int tap = t2 % 9, ic = t2 / 9;
            w_s[(ic*9+tap)*16 + oc] =
                w[(size_t)(ocg0+oc)*IC*9 + (size_t)(ic0+ic)*9 + tap];
        }
        __syncthreads();
        for (int ic = 0; ic < icb; ic++) {
#pragma unroll
            for (int tap = 0; tap < 9; tap++) {
                const int dy = tap/3, dx = tap%3;
                float a0 = in_s[ic][ty+dy][tx+dx];
                float a1 = in_s[ic][ty+4+dy][tx+dx];
                const float4* wp = (const float4*)&w_s[(ic*9+tap)*16];
                float wv[16];
                *(float4*)&wv[0]  = wp[0];
                *(float4*)&wv[4]  = wp[1];
                *(float4*)&wv[8]  = wp[2];
                *(float4*)&wv[12] = wp[3];
#pragma unroll
                for (int oc = 0; oc < 16; oc++) {
                    acc0[oc] = fmaf(a0, wv[oc], acc0[oc]);
                    acc1[oc] = fmaf(a1, wv[oc], acc1[oc]);
                }
            }
        }
    }
    const int pix0 = (y0+ty)*W + (x0+tx);
    const int pix1 = pix0 + 4*W;
#pragma unroll
    for (int oc = 0; oc < 16; oc++) {
        float v0 = acc0[oc], v1 = acc1[oc];
        if (bias) { float b = bias[ocg0+oc]; v0 += b; v1 += b; }
        if (res)  {
            v0 += res[(size_t)(ocg0+oc)*HW + pix0];
            v1 += res[(size_t)(ocg0+oc)*HW + pix1];
        }
        if (do_relu) { v0 = fmaxf(v0, 0.f); v1 = fmaxf(v1, 0.f); }
        out[(size_t)(ocg0+oc)*HW + pix0] = v0;
        out[(size_t)(ocg0+oc)*HW + pix1] = v1;
    }
}

// ---- layer-0 conv: G[p][0:256] = conv3x3(feat64, mw0[0:576]) -> fp16 -------
__global__ void conv_l0_kernel(const float* __restrict__ in,
                               const float* __restrict__ mw0,
                               __half* __restrict__ G)
{
    __shared__ float in_s[16][CTY+2][CTX+2];
    __shared__ float w_s[16*9*16];
    const int tx = threadIdx.x, ty = threadIdx.y;
    const int tid = ty*CTX + tx;
    const int x0 = blockIdx.x*CTX, y0 = blockIdx.y*CTY;
    const int ocg0 = blockIdx.z*16;

    float acc[16];
#pragma unroll
    for (int i = 0; i < 16; i++) acc[i] = 0.f;

    for (int ic0 = 0; ic0 < 64; ic0 += 16) {
        __syncthreads();
        const int tot = 16*(CTY+2)*(CTX+2);
        for (int i = tid; i < tot; i += CTX*CTY) {
            int ic  = i / ((CTY+2)*(CTX+2));
            int rem = i % ((CTY+2)*(CTX+2));
            int ly = rem / (CTX+2), lx = rem % (CTX+2);
            int gy = y0 - 1 + ly, gx = x0 - 1 + lx;
            float v = 0.f;
            if (gy >= 0 && gy < H && gx >= 0 && gx < W)
                v = in[(size_t)(ic0+ic)*HW + gy*W + gx];
            in_s[ic][ly][lx] = v;
        }
        for (int i = tid; i < 16*9*16; i += CTX*CTY) {
            int oc = i & 15;
            int t2 = i >> 4;
            int tap = t2 % 9, ic = t2 / 9;
            w_s[(ic*9+tap)*16 + oc] =
                mw0[(size_t)((ic0+ic)*9 + tap)*256 + ocg0 + oc];
        }
        __syncthreads();
        for (int ic = 0; ic < 16; ic++) {
#pragma unroll
            for (int tap = 0; tap < 9; tap++) {
                const int dy = tap/3, dx = tap%3;
                float a = in_s[ic][ty+dy][tx+dx];
                const float4* wp = (const float4*)&w_s[(ic*9+tap)*16];
                float wv[16];
                *(float4*)&wv[0]  = wp[0];
                *(float4*)&wv[4]  = wp[1];
                *(float4*)&wv[8]  = wp[2];
                *(float4*)&wv[12] = wp[3];
#pragma unroll
                for (int oc = 0; oc < 16; oc++)
                    acc[oc] = fmaf(a, wv[oc], acc[oc]);
            }
        }
    }
    const int pix = (y0+ty)*W + (x0+tx);
#pragma unroll
    for (int oc = 0; oc < 16; oc++)
        G[(size_t)pix*256 + ocg0 + oc] = __float2half(acc[oc]);
}

// ---- prep: fold q_cell into bias ------------------------------------------
__global__ void prep_kernel(const float* __restrict__ mw0,
                            const float* __restrict__ mb0,
                            float* __restrict__ b0eff)
{
    int o = threadIdx.x;
    b0eff[o] = mb0[o] + 0.5f*mw0[578*256 + o] + 0.5f*mw0[579*256 + o];
}

// ---- transpose + fp16: w[K][N] -> wh[N][K] ---------------------------------
__global__ void w_fp16_kernel(const float* __restrict__ w,
                              __half* __restrict__ wh)
{
    int idx = blockIdx.x*256 + threadIdx.x;   // idx = n*256 + k
    int n = idx >> 8, k = idx & 255;
    wh[idx] = __float2half(w[k*256 + n]);
}

// ------------------------------ LIIF query + mma.sync fp16 MLP --------------
#define QB 32
#define SB 128
#define QTHREADS 256
#define ASH 264                       // act row stride in halfs (132 words)
#define WSH 72                        // weight chunk row stride in halfs (36 words)
#define OFF_ACT 0
#define OFF_WB0 67584                 // 128*264*2
#define OFF_WB1 104448                // +256*72*2
#define OFF_BIAS 141312               // +256*72*2
#define DYN_BYTES 142336              // + 256*4

__device__ __forceinline__ void load_wchunk(uint32_t dst_base,
                                            const __half* __restrict__ Wg,
                                            int c, int tid)
{
#pragma unroll
    for (int ii = 0; ii < 8; ii++) {
        int i = tid + ii*QTHREADS;     // 0..2047
        int n = i >> 3, j = i & 7;
        cp_async16(dst_base + (uint32_t)(n*(WSH*2) + j*16),
                   Wg + (size_t)n*256 + c*64 + j*8);
    }
}

__global__ __launch_bounds__(QTHREADS)
void query_kernel(const __half* __restrict__ G,
                  const float* __restrict__ mw0,
                  const float* __restrict__ b0eff,
                  const __half* __restrict__ w1h, const float* __restrict__ b1,
                  const __half* __restrict__ w2h, const float* __restrict__ b2,
                  const __half* __restrict__ w3h, const float* __restrict__ b3,
                  const float* __restrict__ w4, const float* __restrict__ b4,
                  float* __restrict__ out)
{
    extern __shared__ char dyn[];
    uint32_t* actu = (uint32_t*)(dyn + OFF_ACT);       // act as b32 words
    __half*   acth = (__half*)(dyn + OFF_ACT);
    float*    bias_s = (float*)(dyn + OFF_BIAS);
    __shared__ int   p_s[SB];
    __shared__ float relh_s[SB], relw_s[SB], area_s[SB];
    __shared__ float pred_s[SB][4];

    const int tid  = threadIdx.x;
    const int wid  = tid >> 5;
    const int lane = tid & 31;
    const int g    = lane >> 2;     // 0..7
    const int t    = lane & 3;      // 0..3

    const uint32_t dynaddr = smem_u32(dyn);
    const uint32_t wbaddr[2] = {dynaddr + OFF_WB0, dynaddr + OFF_WB1};
    const uint32_t* wbuf[2] = {(const uint32_t*)(dyn + OFF_WB0),
                               (const uint32_t*)(dyn + OFF_WB1)};

    // ---- stage 0: per-sample geometry (mirrors fp32 reference exactly)
    if (tid < SB) {
        int m  = tid;
        int q  = blockIdx.x*QB + (m >> 2);
        int oh = q >> 9, ow = q & 511;
        int r  = (m >> 1) & 1, c = m & 1;
        float sh = (oh + 0.5f)*(2.0f/512.0f) - 1.0f;
        float sw = (ow + 0.5f)*(2.0f/512.0f) - 1.0f;
        const float d = 1.0f/128.0f, EPS = 1e-6f;
        float gh = fminf(fmaxf(sh + (2.f*r - 1.f)*d, -1.f + EPS), 1.f - EPS);
        float gw = fminf(fmaxf(sw + (2.f*c - 1.f)*d, -1.f + EPS), 1.f - EPS);
        float fy = ((gh + 1.0f)*128.0f - 1.0f)*0.5f;
        float fx = ((gw + 1.0f)*128.0f - 1.0f)*0.5f;
        int iy = min(max((int)rintf(fy), 0), 127);
        int ix = min(max((int)rintf(fx), 0), 127);
        float qgh = (iy + 0.5f)*(2.0f/128.0f) - 1.0f;
        float qgw = (ix + 0.5f)*(2.0f/128.0f) - 1.0f;
        float rh = (sh - qgh)*128.0f;
        float rw = (sw - qgw)*128.0f;
        p_s[m] = iy*128 + ix;
        relh_s[m] = rh; relw_s[m] = rw;
        area_s[m] = fabsf(rh*rw);
    }

    // prefetch layer-1 weight chunk 0
    load_wchunk(wbaddr[0], w1h, 0, tid);
    cp_commit();
    __syncthreads();

    // ---- stage 1: A0 = relu(G[p] + rel_h*U + rel_w*V + b0eff) -> fp16
    {
        const int ocw = tid & 127;        // word column (2 neurons)
        const int oc0 = ocw*2;
        float u0 = mw0[576*256 + oc0],     u1 = mw0[576*256 + oc0 + 1];
        float v0 = mw0[577*256 + oc0],     v1 = mw0[577*256 + oc0 + 1];
        float b0v = b0eff[oc0],            b1v = b0eff[oc0 + 1];
        const __half2* G2 = (const __half2*)G;
        for (int m = (tid >> 7); m < SB; m += 2) {
            __half2 gg = G2[(size_t)p_s[m]*128 + ocw];
            float rh = relh_s[m], rw = relw_s[m];
            float x0v = fmaf(rh, u0, fmaf(rw, v0, __low2float(gg)  + b0v));
            float x1v = fmaf(rh, u1, fmaf(rw, v1, __high2float(gg) + b1v));
            __half2 hv = __floats2half2_rn(fmaxf(x0v, 0.f), fmaxf(x1v, 0.f));
            actu[m*(ASH/2) + ocw] = *(const uint32_t*)&hv;
        }
    }
    __syncthreads();

    // ---- stage 2: 3 hidden layers, warp-level fp16 MMA (f32 accumulate)
    const int m0  = (wid & 3)*32;     // warp M origin
    const int n0b = (wid >> 2)*128;   // warp N origin

    const __half* Ws[3] = {w1h, w2h, w3h};
    const float*  Bs[3] = {b1, b2, b3};

    int cnt = 0;   // chunk counter; parity selects buffer
    for (int L = 0; L < 3; L++) {
        bias_s[tid] = Bs[L][tid];

        float acc[2][16][4];
#pragma unroll
        for (int mt = 0; mt < 2; mt++)
#pragma unroll
            for (int nt = 0; nt < 16; nt++)
#pragma unroll
                for (int i = 0; i < 4; i++) acc[mt][nt][i] = 0.f;

        for (int c = 0; c < 4; c++) {         // 4 chunks of K=64
            const bool has_next = (c < 3) || (L < 2);
            if (has_next) {
                const __half* Wn = (c < 3) ? Ws[L] : Ws[L+1];
                const int cn = (c < 3) ? c + 1 : 0;
                load_wchunk(wbaddr[(cnt + 1) & 1], Wn, cn, tid);
                cp_commit();
                cp_wait<1>();
            } else {
                cp_wait<0>();
            }
            __syncthreads();

            const uint32_t* wb = wbuf[cnt & 1];
#pragma unroll
            for (int ks = 0; ks < 4; ks++) {             // k16 steps
                const int kw = c*32 + ks*8;              // act word offset
                uint32_t af[2][4];
#pragma unroll
                for (int mt = 0; mt < 2; mt++) {
                    const uint32_t* ar = actu + (m0 + mt*16 + g)*(ASH/2) + kw + t;
                    af[mt][0] = ar[0];
                    af[mt][2] = ar[4];
                    af[mt][1] = ar[8*(ASH/2)];
                    af[mt][3] = ar[8*(ASH/2) + 4];
                }
                const uint32_t* wp = wb + (size_t)(n0b + g)*(WSH/2) + ks*8 + t;
#pragma unroll
                for (int nt = 0; nt < 16; nt++) {
                    uint32_t b0 = wp[nt*8*(WSH/2)];
                    uint32_t b1r = wp[nt*8*(WSH/2) + 4];
                    mma16(acc[0][nt], af[0][0], af[0][1], af[0][2], af[0][3], b0, b1r);
                    mma16(acc[1][nt], af[1][0], af[1][1], af[1][2], af[1][3], b0, b1r);
                }
            }
            cnt++;
            __syncthreads();
        }

        // ---- epilogue: acc + bias -> relu -> act (fp16 half2 stores)
#pragma unroll
        for (int mt = 0; mt < 2; mt++) {
            const int r0 = m0 + mt*16 + g;
#pragma unroll
            for (int nt = 0; nt < 16; nt++) {
                const int col = n0b + nt*8 + 2*t;
                float v0 = fmaxf(acc[mt][nt][0] + bias_s[col],     0.f);
                float v1 = fmaxf(acc[mt][nt][1] + bias_s[col + 1], 0.f);
                float v2 = fmaxf(acc[mt][nt][2] + bias_s[col],     0.f);
                float v3 = fmaxf(acc[mt][nt][3] + bias_s[col + 1], 0.f);
                __half2 h01 = __floats2half2_rn(v0, v1);
                __half2 h23 = __floats2half2_rn(v2, v3);
                const int cw = (n0b >> 1) + nt*4 + t;
                actu[r0*(ASH/2) + cw]     = *(const uint32_t*)&h01;
                actu[(r0+8)*(ASH/2) + cw] = *(const uint32_t*)&h23;
            }
        }
        __syncthreads();
    }

    // ---- stage 3: output layer 256->3 (fp32 accumulate over fp16 acts)
    {
        float* wsm = (float*)(dyn + OFF_WB0);   // weight buffers free now
        for (int i = tid; i < 768; i += QTHREADS) wsm[i] = w4[i];
        __syncthreads();
        if (tid < SB) {
            const __half* ap = acth + tid*ASH;
            float s0 = b4[0], s1 = b4[1], s2 = b4[2];
#pragma unroll 4
            for (int k = 0; k < 256; k++) {
                float a = __half2float(ap[k]);
                s0 = fmaf(a, wsm[k*3 + 0], s0);
                s1 = fmaf(a, wsm[k*3 + 1], s1);
                s2 = fmaf(a, wsm[k*3 + 2], s2);
            }
            pred_s[tid][0] = s0; pred_s[tid][1] = s1; pred_s[tid][2] = s2;
        }
    }
    __syncthreads();

    // ---- stage 4: LIIF ensemble (diagonal areas) + clip
    if (tid < QB) {
        int bb = tid*4;
        float a0 = area_s[bb+0], a1 = area_s[bb+1];
        float a2 = area_s[bb+2], a3 = area_s[bb+3];
        float tot = a0 + a1 + a2 + a3 + 1e-9f;
        int q = blockIdx.x*QB + tid;
#pragma unroll
        for (int j = 0; j < 3; j++) {
            float num = pred_s[bb+0][j]*a3 + pred_s[bb+1][j]*a2
                      + pred_s[bb+2][j]*a1 + pred_s[bb+3][j]*a0;
            float yv = num / tot;
            yv = fminf(fmaxf(yv, 0.f), 1.f);
            out[(size_t)j*NQ + q] = yv;
        }
    }
}

// ------------------------------ launch --------------------------------------
extern "C" void kernel_launch(void* const* d_in, const int* in_sizes, int n_in,
                              void* d_out, int out_size)
{
    const float* x      = (const float*)d_in[0];
    const float* head_w = (const float*)d_in[2];
    const float* head_b = (const float*)d_in[3];
    const float* rb_w   = (const float*)d_in[4];
    const float* rb_b   = (const float*)d_in[5];
    const float* tail_w = (const float*)d_in[6];
    const float* tail_b = (const float*)d_in[7];
    const float* mw0 = (const float*)d_in[8];
    const float* mb0 = (const float*)d_in[9];
    const float* mw1 = (const float*)d_in[10];
    const float* mb1 = (const float*)d_in[11];
    const float* mw2 = (const float*)d_in[12];
    const float* mb2 = (const float*)d_in[13];
    const float* mw3 = (const float*)d_in[14];
    const float* mb3 = (const float*)d_in[15];
    const float* mw4 = (const float*)d_in[16];
    const float* mb4 = (const float*)d_in[17];
    float* out = (float*)d_out;

    float *h0, *A, *B, *C, *b0eff;
    __half *G, *w1h, *w2h, *w3h;
    cudaGetSymbolAddress((void**)&h0, g_h0);
    cudaGetSymbolAddress((void**)&A,  g_A);
    cudaGetSymbolAddress((void**)&B,  g_B);
    cudaGetSymbolAddress((void**)&C,  g_C);
    cudaGetSymbolAddress((void**)&G,  g_G);
    cudaGetSymbolAddress((void**)&b0eff, g_b0eff);
    cudaGetSymbolAddress((void**)&w1h, g_w1h);
    cudaGetSymbolAddress((void**)&w2h, g_w2h);
    cudaGetSymbolAddress((void**)&w3h, g_w3h);

    dim3 cb(CTX, CTY);
    dim3 cg(W/CTX, H/TILEY, 4);     // 2 pixels per thread

    // EDSR encoder
    conv3x3_kernel<<<cg, cb>>>(x, head_w, head_b, nullptr, h0, 3, 0);
    const float* hcur = h0;
    float* pp[2] = {A, C};
    for (int i = 0; i < 16; i++) {
        conv3x3_kernel<<<cg, cb>>>(hcur, rb_w + (size_t)(2*i)*36864,
                                   rb_b + 2*i*64, nullptr, B, 64, 1);
        float* ho = pp[i & 1];
        conv3x3_kernel<<<cg, cb>>>(B, rb_w + (size_t)(2*i+1)*36864,
                                   rb_b + (2*i+1)*64, hcur, ho, 64, 0);
        hcur = ho;
    }
    conv3x3_kernel<<<cg, cb>>>(hcur, tail_w, tail_b, h0, B, 64, 0); // feat in B

    // layer-0-as-conv: G[16384][256] fp16
    dim3 lb(CTX, CTY);
    dim3 lg(W/CTX, H/CTY, 16);
    conv_l0_kernel<<<lg, lb>>>(B, mw0, G);

    prep_kernel<<<1, 256>>>(mw0, mb0, b0eff);

    // fp16 transposed hidden-layer weights [N][K]
    w_fp16_kernel<<<256, 256>>>(mw1, w1h);
    w_fp16_kernel<<<256, 256>>>(mw2, w2h);
    w_fp16_kernel<<<256, 256>>>(mw3, w3h);

    cudaFuncSetAttribute(query_kernel,
                         cudaFuncAttributeMaxDynamicSharedMemorySize,
                         DYN_BYTES);
    query_kernel<<<NQ/QB, QTHREADS, DYN_BYTES>>>(
        G, mw0, b0eff, w1h, mb1, w2h, mb2, w3h, mb3, mw4, mb4, out);
}

// round 5
// speedup vs baseline: 5.5414x; 2.2292x over previous
#include <cuda_runtime.h>
#include <cuda_fp16.h>
#include <cstdint>

#define H 128
#define W 128
#define HW 16384
#define OH 512
#define OWID 512
#define NQ (OH*OWID)

// ------------------------------ scratch (device globals, no allocation) ----
__device__ __align__(16) float g_h0[64*HW];      // NHWC
__device__ __align__(16) float g_A [64*HW];
__device__ __align__(16) float g_B [64*HW];
__device__ __align__(16) float g_C [64*HW];
__device__ __align__(16) __half g_G [(size_t)HW*256];
__device__ float g_b0eff[256];
__device__ __align__(16) __half g_w1h[65536];    // fp16, [N][K]
__device__ __align__(16) __half g_w2h[65536];
__device__ __align__(16) __half g_w3h[65536];
__device__ __align__(16) uint32_t g_wt [33*36864];  // tf32 conv weights (32 rb + tail)
__device__ __align__(16) uint32_t g_wl0[4*36864];   // tf32 layer-0 conv weights

// ------------------------------ PTX helpers --------------------------------
__device__ __forceinline__ uint32_t smem_u32(const void* p) {
    uint32_t a;
    asm("{ .reg .u64 t; cvta.to.shared.u64 t, %1; cvt.u32.u64 %0, t; }"
        : "=r"(a) : "l"(p));
    return a;
}
__device__ __forceinline__ uint32_t f2tf32(float x) {
    uint32_t r; asm("cvt.rna.tf32.f32 %0, %1;" : "=r"(r) : "f"(x)); return r;
}
__device__ __forceinline__ void cp_async16(uint32_t dst, const void* src) {
    asm volatile("cp.async.ca.shared.global [%0], [%1], 16;"
                 :: "r"(dst), "l"(src) : "memory");
}
__device__ __forceinline__ void cp_commit() {
    asm volatile("cp.async.commit_group;" ::: "memory");
}
template<int N> __device__ __forceinline__ void cp_wait() {
    asm volatile("cp.async.wait_group %0;" :: "n"(N) : "memory");
}
// m16n8k8 tf32 MMA, A row-major, B col-major, f32 accumulate (in-place)
__device__ __forceinline__ void mma8(float* d,
                                     uint32_t a0, uint32_t a1, uint32_t a2, uint32_t a3,
                                     uint32_t b0, uint32_t b1) {
    asm volatile(
        "mma.sync.aligned.m16n8k8.row.col.f32.tf32.tf32.f32 "
        "{%0,%1,%2,%3},{%4,%5,%6,%7},{%8,%9},{%0,%1,%2,%3};"
        : "+f"(d[0]), "+f"(d[1]), "+f"(d[2]), "+f"(d[3])
        : "r"(a0), "r"(a1), "r"(a2), "r"(a3), "r"(b0), "r"(b1));
}
// m16n8k16 f16 MMA
__device__ __forceinline__ void mma16(float* d,
                                      uint32_t a0, uint32_t a1, uint32_t a2, uint32_t a3,
                                      uint32_t b0, uint32_t b1) {
    asm volatile(
        "mma.sync.aligned.m16n8k16.row.col.f32.f16.f16.f32 "
        "{%0,%1,%2,%3},{%4,%5,%6,%7},{%8,%9},{%0,%1,%2,%3};"
        : "+f"(d[0]), "+f"(d[1]), "+f"(d[2]), "+f"(d[3])
        : "r"(a0), "r"(a1), "r"(a2), "r"(a3), "r"(b0), "r"(b1));
}

// ------------------------------ head conv (IC=3), NCHW in -> NHWC out -------
#define CTX 32
#define CTY 4
__global__ void conv_head(const float* __restrict__ x,
                          const float* __restrict__ w,
                          const float* __restrict__ bias,
                          float* __restrict__ out)
{
    __shared__ float in_s[3][CTY+2][CTX+2];
    __shared__ float w_s[3*9*16];
    const int tx = threadIdx.x, ty = threadIdx.y;
    const int tid = ty*CTX + tx;
    const int x0 = blockIdx.x*CTX, y0 = blockIdx.y*CTY;
    const int ocg0 = blockIdx.z*16;

    float acc[16];
#pragma unroll
    for (int i = 0; i < 16; i++) acc[i] = 0.f;

    const int tot = 3*(CTY+2)*(CTX+2);
    for (int i = tid; i < tot; i += CTX*CTY) {
        int ic  = i / ((CTY+2)*(CTX+2));
        int rem = i % ((CTY+2)*(CTX+2));
        int ly = rem / (CTX+2), lx = rem % (CTX+2);
        int gy = y0 - 1 + ly, gx = x0 - 1 + lx;
        float v = 0.f;
        if (gy >= 0 && gy < H && gx >= 0 && gx < W)
            v = x[(size_t)ic*HW + gy*W + gx];
        in_s[ic][ly][lx] = v;
    }
    for (int i = tid; i < 3*9*16; i += CTX*CTY) {
        int oc = i & 15;
        int t2 = i >> 4;
        int tap = t2 % 9, ic = t2 / 9;
        w_s[(ic*9+tap)*16 + oc] = w[(size_t)(ocg0+oc)*27 + ic*9 + tap];
    }
    __syncthreads();
    for (int ic = 0; ic < 3; ic++) {
#pragma unroll
        for (int tap = 0; tap < 9; tap++) {
            const int dy = tap/3, dx = tap%3;
            float a = in_s[ic][ty+dy][tx+dx];
            const float4* wp = (const float4*)&w_s[(ic*9+tap)*16];
            float wv[16];
            *(float4*)&wv[0]  = wp[0];
            *(float4*)&wv[4]  = wp[1];
            *(float4*)&wv[8]  = wp[2];
            *(float4*)&wv[12] = wp[3];
#pragma unroll
            for (int oc = 0; oc < 16; oc++)
                acc[oc] = fmaf(a, wv[oc], acc[oc]);
        }
    }
    const int pix = (y0+ty)*W + (x0+tx);
    float4* o4 = (float4*)(out + (size_t)pix*64 + ocg0);
#pragma unroll
    for (int v = 0; v < 4; v++) {
        float4 r;
        r.x = acc[v*4+0] + bias[ocg0+v*4+0];
        r.y = acc[v*4+1] + bias[ocg0+v*4+1];
        r.z = acc[v*4+2] + bias[ocg0+v*4+2];
        r.w = acc[v*4+3] + bias[ocg0+v*4+3];
        o4[v] = r;
    }
}

// ------------------------------ weight transforms ---------------------------
// dst layout per conv: [tap(9)][icc(8)][n(64)][j(8)], j = t*2+s, ic = icc*8+t+4s
__global__ void prep_wt(const float* __restrict__ rb_w,
                        const float* __restrict__ tail_w,
                        uint32_t* __restrict__ wt)
{
    int i = blockIdx.x*256 + threadIdx.x;       // < 33*36864
    int cv = i / 36864;
    int r  = i % 36864;
    int tap = r >> 12;
    int r2  = r & 4095;
    int icc = r2 >> 9;
    int r3  = r2 & 511;
    int n   = r3 >> 3;
    int j   = r3 & 7;
    int t = j >> 1, s = j & 1;
    int ic = icc*8 + t + 4*s;
    const float* src = (cv < 32) ? (rb_w + (size_t)cv*36864) : tail_w;
    wt[i] = f2tf32(src[(size_t)n*576 + ic*9 + tap]);
}

__global__ void prep_wl0(const float* __restrict__ mw0,
                         uint32_t* __restrict__ wl0)
{
    int i = blockIdx.x*256 + threadIdx.x;       // < 4*36864
    int grp = i / 36864;
    int r  = i % 36864;
    int tap = r >> 12;
    int r2  = r & 4095;
    int icc = r2 >> 9;
    int r3  = r2 & 511;
    int n   = r3 >> 3;
    int j   = r3 & 7;
    int t = j >> 1, s = j & 1;
    int ic = icc*8 + t + 4*s;
    int ng = grp*64 + n;
    wl0[i] = f2tf32(mw0[(size_t)(ic*9 + tap)*256 + ng]);
}

// ------------------------------ implicit-GEMM 3x3 conv (tf32 tensor) --------
// CTA: 64 pixels (half image row) x 64 oc. 4 warps, each M32 x N32.
// MODE 0: out = relu(acc + bias)   (fp32 NHWC)
// MODE 1: out = acc + bias + res   (fp32 NHWC)
// MODE 2: outh = acc (fp16, [p][256], oc group = blockIdx.z)
#define STRIPW 72
#define GSMEM ((3*66*STRIPW + 2*4096)*4)

template<int MODE>
__global__ void __launch_bounds__(128) conv_gemm(
    const float* __restrict__ in, const uint32_t* __restrict__ wt,
    const float* __restrict__ bias, const float* __restrict__ res,
    float* __restrict__ out, __half* __restrict__ outh)
{
    extern __shared__ uint32_t sm[];
    uint32_t* strip = sm;                    // 3*66*72 = 14256 words
    uint32_t* wbuf  = sm + 3*66*STRIPW;      // 2*4096 words
    __shared__ float bias_s[64];

    const int tid = threadIdx.x, wid = tid >> 5, lane = tid & 31;
    const int g = lane >> 2, t = lane & 3;
    const int y = blockIdx.x >> 1, x0 = (blockIdx.x & 1)*64;
    const uint32_t* wconv = (MODE == 2) ? wt + (size_t)blockIdx.z*36864 : wt;

    if (MODE != 2 && tid < 64) bias_s[tid] = bias[tid];

    // ---- strip load: rows y-1..y+1, cols x0-1..x0+64, 64 ch, permuted tf32
    const float4* in4 = (const float4*)in;
    for (int i = tid; i < 3168; i += 128) {
        int r = i / 1056, rem = i - r*1056;
        int j = rem >> 4, q = rem & 15;
        int gy = y - 1 + r, gx = x0 - 1 + j;
        uint32_t v0 = 0, v1 = 0, v2 = 0, v3 = 0;
        if (gy >= 0 && gy < H && gx >= 0 && gx < W) {
            float4 v = in4[(size_t)(gy*W + gx)*16 + q];
            v0 = f2tf32(v.x); v1 = f2tf32(v.y); v2 = f2tf32(v.z); v3 = f2tf32(v.w);
        }
        uint32_t base = (uint32_t)(r*66 + j)*STRIPW + ((q >> 1) << 3) + (q & 1);
        strip[base]     = v0;
        strip[base + 2] = v1;
        strip[base + 4] = v2;
        strip[base + 6] = v3;
    }

    // ---- prefetch tap 0 weights
    const uint32_t wbase = smem_u32(sm) + 3*66*STRIPW*4;
#pragma unroll
    for (int ii = 0; ii < 8; ii++) {
        int i = tid + ii*128;
        cp_async16(wbase + (uint32_t)i*16, wconv + i*4);
    }
    cp_commit();

    float acc[2][4][4];
#pragma unroll
    for (int a = 0; a < 2; a++)
#pragma unroll
        for (int b = 0; b < 4; b++)
#pragma unroll
            for (int c = 0; c < 4; c++) acc[a][b][c] = 0.f;

    const int m0 = (wid & 1)*32, n0 = (wid >> 1)*32;

    for (int tap = 0; tap < 9; tap++) {
        if (tap < 8) {
            uint32_t db = wbase + ((tap + 1) & 1)*4096u*4u;
            const uint32_t* src = wconv + (size_t)(tap + 1)*4096;
#pragma unroll
            for (int ii = 0; ii < 8; ii++) {
                int i = tid + ii*128;
                cp_async16(db + (uint32_t)i*16, src + i*4);
            }
            cp_commit();
            cp_wait<1>();
        } else {
            cp_wait<0>();
        }
        __syncthreads();

        const uint32_t* wb = wbuf + (tap & 1)*4096;
        const uint32_t* arow = strip
            + (uint32_t)(((tap/3)*66 + (tap%3) + m0 + g)*STRIPW) + t*2;
#pragma unroll
        for (int icc = 0; icc < 8; icc++) {
            uint2 a0 = *(const uint2*)(arow + icc*8);
            uint2 a1 = *(const uint2*)(arow + icc*8 + 8*STRIPW);
            uint2 a2 = *(const uint2*)(arow + icc*8 + 16*STRIPW);
            uint2 a3 = *(const uint2*)(arow + icc*8 + 24*STRIPW);
            uint2 bf[4];
#pragma unroll
            for (int nt = 0; nt < 4; nt++)
                bf[nt] = *(const uint2*)(wb + icc*512 + (n0 + nt*8 + g)*8 + t*2);
#pragma unroll
            for (int nt = 0; nt < 4; nt++) {
                mma8(acc[0][nt], a0.x, a1.x, a0.y, a1.y, bf[nt].x, bf[nt].y);
                mma8(acc[1][nt], a2.x, a3.x, a2.y, a3.y, bf[nt].x, bf[nt].y);
            }
        }
        __syncthreads();
    }

    // ---- epilogue
    const int pix0 = y*W + x0;
#pragma unroll
    for (int mt = 0; mt < 2; mt++) {
        const int pr = pix0 + m0 + mt*16 + g;
#pragma unroll
        for (int nt = 0; nt < 4; nt++) {
            const int c0 = n0 + nt*8 + 2*t;
            float v0 = acc[mt][nt][0], v1 = acc[mt][nt][1];
            float v2 = acc[mt][nt][2], v3 = acc[mt][nt][3];
            if (MODE == 0) {
                float b0 = bias_s[c0], b1 = bias_s[c0+1];
                v0 = fmaxf(v0 + b0, 0.f); v1 = fmaxf(v1 + b1, 0.f);
                v2 = fmaxf(v2 + b0, 0.f); v3 = fmaxf(v3 + b1, 0.f);
            } else if (MODE == 1) {
                float b0 = bias_s[c0], b1 = bias_s[c0+1];
                float2 r0 = *(const float2*)(res + (size_t)pr*64 + c0);
                float2 r1 = *(const float2*)(res + (size_t)(pr+8)*64 + c0);
                v0 += b0 + r0.x; v1 += b1 + r0.y;
                v2 += b0 + r1.x; v3 += b1 + r1.y;
            }
            if (MODE != 2) {
                float2 s0 = {v0, v1}, s1 = {v2, v3};
                *(float2*)(out + (size_t)pr*64 + c0) = s0;
                *(float2*)(out + (size_t)(pr+8)*64 + c0) = s1;
            } else {
                const int cc = blockIdx.z*64 + c0;
                __half2 h0 = __floats2half2_rn(v0, v1);
                __half2 h1 = __floats2half2_rn(v2, v3);
                *(__half2*)(outh + (size_t)pr*256 + cc) = h0;
                *(__half2*)(outh + (size_t)(pr+8)*256 + cc) = h1;
            }
        }
    }
}

// ---- prep: fold q_cell into bias ------------------------------------------
__global__ void prep_kernel(const float* __restrict__ mw0,
                            const float* __restrict__ mb0,
                            float* __restrict__ b0eff)
{
    int o = threadIdx.x;
    b0eff[o] = mb0[o] + 0.5f*mw0[578*256 + o] + 0.5f*mw0[579*256 + o];
}

// ---- transpose + fp16: w[K][N] -> wh[N][K] ---------------------------------
__global__ void w_fp16_kernel(const float* __restrict__ w,
                              __half* __restrict__ wh)
{
    int idx = blockIdx.x*256 + threadIdx.x;
    int n = idx >> 8, k = idx & 255;
    wh[idx] = __float2half(w[k*256 + n]);
}

// ------------------------------ LIIF query + mma.sync fp16 MLP --------------
#define QB 32
#define SB 128
#define QTHREADS 256
#define ASH 264
#define WSH 72
#define OFF_ACT 0
#define OFF_WB0 67584
#define OFF_WB1 104448
#define OFF_BIAS 141312
#define DYN_BYTES 142336

__device__ __forceinline__ void load_wchunk(uint32_t dst_base,
                                            const __half* __restrict__ Wg,
                                            int c, int tid)
{
#pragma unroll
    for (int ii = 0; ii < 8; ii++) {
        int i = tid + ii*QTHREADS;
        int n = i >> 3, j = i & 7;
        cp_async16(dst_base + (uint32_t)(n*(WSH*2) + j*16),
                   Wg + (size_t)n*256 + c*64 + j*8);
    }
}

__global__ __launch_bounds__(QTHREADS)
void query_kernel(const __half* __restrict__ G,
                  const float* __restrict__ mw0,
                  const float* __restrict__ b0eff,
                  const __half* __restrict__ w1h, const float* __restrict__ b1,
                  const __half* __restrict__ w2h, const float* __restrict__ b2,
                  const __half* __restrict__ w3h, const float* __restrict__ b3,
                  const float* __restrict__ w4, const float* __restrict__ b4,
                  float* __restrict__ out)
{
    extern __shared__ char dyn[];
    uint32_t* actu = (uint32_t*)(dyn + OFF_ACT);
    __half*   acth = (__half*)(dyn + OFF_ACT);
    float*    bias_s = (float*)(dyn + OFF_BIAS);
    __shared__ int   p_s[SB];
    __shared__ float relh_s[SB], relw_s[SB], area_s[SB];
    __shared__ float pred_s[SB][4];

    const int tid  = threadIdx.x;
    const int wid  = tid >> 5;
    const int lane = tid & 31;
    const int g    = lane >> 2;
    const int t    = lane & 3;

    const uint32_t dynaddr = smem_u32(dyn);
    const uint32_t wbaddr[2] = {dynaddr + OFF_WB0, dynaddr + OFF_WB1};
    const uint32_t* wbuf[2] = {(const uint32_t*)(dyn + OFF_WB0),
                               (const uint32_t*)(dyn + OFF_WB1)};

    if (tid < SB) {
        int m  = tid;
        int q  = blockIdx.x*QB + (m >> 2);
        int oh = q >> 9, ow = q & 511;
        int r  = (m >> 1) & 1, c = m & 1;
        float sh = (oh + 0.5f)*(2.0f/512.0f) - 1.0f;
        float sw = (ow + 0.5f)*(2.0f/512.0f) - 1.0f;
        const float d = 1.0f/128.0f, EPS = 1e-6f;
        float gh = fminf(fmaxf(sh + (2.f*r - 1.f)*d, -1.f + EPS), 1.f - EPS);
        float gw = fminf(fmaxf(sw + (2.f*c - 1.f)*d, -1.f + EPS), 1.f - EPS);
        float fy = ((gh + 1.0f)*128.0f - 1.0f)*0.5f;
        float fx = ((gw + 1.0f)*128.0f - 1.0f)*0.5f;
        int iy = min(max((int)rintf(fy), 0), 127);
        int ix = min(max((int)rintf(fx), 0), 127);
        float qgh = (iy + 0.5f)*(2.0f/128.0f) - 1.0f;
        float qgw = (ix + 0.5f)*(2.0f/128.0f) - 1.0f;
        float rh = (sh - qgh)*128.0f;
        float rw = (sw - qgw)*128.0f;
        p_s[m] = iy*128 + ix;
        relh_s[m] = rh; relw_s[m] = rw;
        area_s[m] = fabsf(rh*rw);
    }

    load_wchunk(wbaddr[0], w1h, 0, tid);
    cp_commit();
    __syncthreads();

    {
        const int ocw = tid & 127;
        const int oc0 = ocw*2;
        float u0 = mw0[576*256 + oc0],     u1 = mw0[576*256 + oc0 + 1];
        float v0 = mw0[577*256 + oc0],     v1 = mw0[577*256 + oc0 + 1];
        float b0v = b0eff[oc0],            b1v = b0eff[oc0 + 1];
        const __half2* G2 = (const __half2*)G;
        for (int m = (tid >> 7); m < SB; m += 2) {
            __half2 gg = G2[(size_t)p_s[m]*128 + ocw];
            float rh = relh_s[m], rw = relw_s[m];
            float x0v = fmaf(rh, u0, fmaf(rw, v0, __low2float(gg)  + b0v));
            float x1v = fmaf(rh, u1, fmaf(rw, v1, __high2float(gg) + b1v));
            __half2 hv = __floats2half2_rn(fmaxf(x0v, 0.f), fmaxf(x1v, 0.f));
            actu[m*(ASH/2) + ocw] = *(const uint32_t*)&hv;
        }
    }
    __syncthreads();

    const int m0  = (wid & 3)*32;
    const int n0b = (wid >> 2)*128;

    const __half* Ws[3] = {w1h, w2h, w3h};
    const float*  Bs[3] = {b1, b2, b3};

    int cnt = 0;
    for (int L = 0; L < 3; L++) {
        bias_s[tid] = Bs[L][tid];

        float acc[2][16][4];
#pragma unroll
        for (int mt = 0; mt < 2; mt++)
#pragma unroll
            for (int nt = 0; nt < 16; nt++)
#pragma unroll
                for (int i = 0; i < 4; i++) acc[mt][nt][i] = 0.f;

        for (int c = 0; c < 4; c++) {
            const bool has_next = (c < 3) || (L < 2);
            if (has_next) {
                const __half* Wn = (c < 3) ? Ws[L] : Ws[L+1];
                const int cn = (c < 3) ? c + 1 : 0;
                load_wchunk(wbaddr[(cnt + 1) & 1], Wn, cn, tid);
                cp_commit();
                cp_wait<1>();
            } else {
                cp_wait<0>();
            }
            __syncthreads();

            const uint32_t* wb = wbuf[cnt & 1];
#pragma unroll
            for (int ks = 0; ks < 4; ks++) {
                const int kw = c*32 + ks*8;
                uint32_t af[2][4];
#pragma unroll
                for (int mt = 0; mt < 2; mt++) {
                    const uint32_t* ar = actu + (m0 + mt*16 + g)*(ASH/2) + kw + t;
                    af[mt][0] = ar[0];
                    af[mt][2] = ar[4];
                    af[mt][1] = ar[8*(ASH/2)];
                    af[mt][3] = ar[8*(ASH/2) + 4];
                }
                const uint32_t* wp = wb + (size_t)(n0b + g)*(WSH/2) + ks*8 + t;
#pragma unroll
                for (int nt = 0; nt < 16; nt++) {
                    uint32_t b0 = wp[nt*8*(WSH/2)];
                    uint32_t b1r = wp[nt*8*(WSH/2) + 4];
                    mma16(acc[0][nt], af[0][0], af[0][1], af[0][2], af[0][3], b0, b1r);
                    mma16(acc[1][nt], af[1][0], af[1][1], af[1][2], af[1][3], b0, b1r);
                }
            }
            cnt++;
            __syncthreads();
        }

#pragma unroll
        for (int mt = 0; mt < 2; mt++) {
            const int r0 = m0 + mt*16 + g;
#pragma unroll
            for (int nt = 0; nt < 16; nt++) {
                const int col = n0b + nt*8 + 2*t;
                float v0 = fmaxf(acc[mt][nt][0] + bias_s[col],     0.f);
                float v1 = fmaxf(acc[mt][nt][1] + bias_s[col + 1], 0.f);
                float v2 = fmaxf(acc[mt][nt][2] + bias_s[col],     0.f);
                float v3 = fmaxf(acc[mt][nt][3] + bias_s[col + 1], 0.f);
                __half2 h01 = __floats2half2_rn(v0, v1);
                __half2 h23 = __floats2half2_rn(v2, v3);
                const int cw = (n0b >> 1) + nt*4 + t;
                actu[r0*(ASH/2) + cw]     = *(const uint32_t*)&h01;
                actu[(r0+8)*(ASH/2) + cw] = *(const uint32_t*)&h23;
            }
        }
        __syncthreads();
    }

    {
        float* wsm = (float*)(dyn + OFF_WB0);
        for (int i = tid; i < 768; i += QTHREADS) wsm[i] = w4[i];
        __syncthreads();
        if (tid < SB) {
            const __half* ap = acth + tid*ASH;
            float s0 = b4[0], s1 = b4[1], s2 = b4[2];
#pragma unroll 4
            for (int k = 0; k < 256; k++) {
                float a = __half2float(ap[k]);
                s0 = fmaf(a, wsm[k*3 + 0], s0);
                s1 = fmaf(a, wsm[k*3 + 1], s1);
                s2 = fmaf(a, wsm[k*3 + 2], s2);
            }
            pred_s[tid][0] = s0; pred_s[tid][1] = s1; pred_s[tid][2] = s2;
        }
    }
    __syncthreads();

    if (tid < QB) {
        int bb = tid*4;
        float a0 = area_s[bb+0], a1 = area_s[bb+1];
        float a2 = area_s[bb+2], a3 = area_s[bb+3];
        float tot = a0 + a1 + a2 + a3 + 1e-9f;
        int q = blockIdx.x*QB + tid;
#pragma unroll
        for (int j = 0; j < 3; j++) {
            float num = pred_s[bb+0][j]*a3 + pred_s[bb+1][j]*a2
                      + pred_s[bb+2][j]*a1 + pred_s[bb+3][j]*a0;
            float yv = num / tot;
            yv = fminf(fmaxf(yv, 0.f), 1.f);
            out[(size_t)j*NQ + q] = yv;
        }
    }
}

// ------------------------------ launch --------------------------------------
extern "C" void kernel_launch(void* const* d_in, const int* in_sizes, int n_in,
                              void* d_out, int out_size)
{
    const float* x      = (const float*)d_in[0];
    const float* head_w = (const float*)d_in[2];
    const float* head_b = (const float*)d_in[3];
    const float* rb_w   = (const float*)d_in[4];
    const float* rb_b   = (const float*)d_in[5];
    const float* tail_w = (const float*)d_in[6];
    const float* tail_b = (const float*)d_in[7];
    const float* mw0 = (const float*)d_in[8];
    const float* mb0 = (const float*)d_in[9];
    const float* mw1 = (const float*)d_in[10];
    const float* mb1 = (const float*)d_in[11];
    const float* mw2 = (const float*)d_in[12];
    const float* mb2 = (const float*)d_in[13];
    const float* mw3 = (const float*)d_in[14];
    const float* mb3 = (const float*)d_in[15];
    const float* mw4 = (const float*)d_in[16];
    const float* mb4 = (const float*)d_in[17];
    float* out = (float*)d_out;

    float *h0, *A, *B, *C, *b0eff;
    __half *G, *w1h, *w2h, *w3h;
    uint32_t *wt, *wl0;
    cudaGetSymbolAddress((void**)&h0, g_h0);
    cudaGetSymbolAddress((void**)&A,  g_A);
    cudaGetSymbolAddress((void**)&B,  g_B);
    cudaGetSymbolAddress((void**)&C,  g_C);
    cudaGetSymbolAddress((void**)&G,  g_G);
    cudaGetSymbolAddress((void**)&b0eff, g_b0eff);
    cudaGetSymbolAddress((void**)&w1h, g_w1h);
    cudaGetSymbolAddress((void**)&w2h, g_w2h);
    cudaGetSymbolAddress((void**)&w3h, g_w3h);
    cudaGetSymbolAddress((void**)&wt,  g_wt);
    cudaGetSymbolAddress((void**)&wl0, g_wl0);

    // weight transforms
    prep_wt <<<(33*36864)/256, 256>>>(rb_w, tail_w, wt);
    prep_wl0<<<(4*36864)/256, 256>>>(mw0, wl0);
    prep_kernel<<<1, 256>>>(mw0, mb0, b0eff);
    w_fp16_kernel<<<256, 256>>>(mw1, w1h);
    w_fp16_kernel<<<256, 256>>>(mw2, w2h);
    w_fp16_kernel<<<256, 256>>>(mw3, w3h);

    cudaFuncSetAttribute(conv_gemm<0>, cudaFuncAttributeMaxDynamicSharedMemorySize, GSMEM);
    cudaFuncSetAttribute(conv_gemm<1>, cudaFuncAttributeMaxDynamicSharedMemorySize, GSMEM);
    cudaFuncSetAttribute(conv_gemm<2>, cudaFuncAttributeMaxDynamicSharedMemorySize, GSMEM);

    // head conv -> NHWC h0
    conv_head<<<dim3(W/CTX, H/CTY, 4), dim3(CTX, CTY)>>>(x, head_w, head_b, h0);

    // 16 resblocks (NHWC, tensor-core)
    const float* hcur = h0;
    float* pp[2] = {A, C};
    for (int i = 0; i < 16; i++) {
        conv_gemm<0><<<256, 128, GSMEM>>>(hcur, wt + (size_t)(2*i)*36864,
                                          rb_b + 2*i*64, nullptr, B, nullptr);
        float* ho = pp[i & 1];
        conv_gemm<1><<<256, 128, GSMEM>>>(B, wt + (size_t)(2*i+1)*36864,
                                          rb_b + (2*i+1)*64, hcur, ho, nullptr);
        hcur = ho;
    }
    // tail conv + global residual -> feat in B
    conv_gemm<1><<<256, 128, GSMEM>>>(hcur, wt + (size_t)32*36864,
                                      tail_b, h0, B, nullptr);

    // layer-0-as-conv: G[16384][256] fp16
    conv_gemm<2><<<dim3(256, 1, 4), 128, GSMEM>>>(B, wl0, nullptr, nullptr,
                                                  nullptr, G);

    cudaFuncSetAttribute(query_kernel,
                         cudaFuncAttributeMaxDynamicSharedMemorySize,
                         DYN_BYTES);
    query_kernel<<<NQ/QB, QTHREADS, DYN_BYTES>>>(
        G, mw0, b0eff, w1h, mb1, w2h, mb2, w3h, mb3, mw4, mb4, out);
}

// round 6
// speedup vs baseline: 6.1120x; 1.1030x over previous
#include <cuda_runtime.h>
#include <cuda_fp16.h>
#include <cstdint>

#define H 128
#define W 128
#define HW 16384
#define OH 512
#define OWID 512
#define NQ (OH*OWID)

// ------------------------------ scratch (device globals, no allocation) ----
__device__ __align__(16) float g_h0[64*HW];      // NHWC
__device__ __align__(16) float g_A [64*HW];
__device__ __align__(16) float g_B [64*HW];
__device__ __align__(16) float g_C [64*HW];
__device__ __align__(16) __half g_G [(size_t)HW*256];
__device__ float g_b0eff[256];
__device__ __align__(16) __half g_w1h[65536];    // fp16 MLP weights, [N][K]
__device__ __align__(16) __half g_w2h[65536];
__device__ __align__(16) __half g_w3h[65536];
__device__ __align__(16) __half g_wch[33*36864]; // fp16 conv weights [cv][tap][n][ic]
__device__ __align__(16) __half g_wl0[4*36864];  // fp16 layer-0 conv weights

// ------------------------------ PTX helpers --------------------------------
__device__ __forceinline__ uint32_t smem_u32(const void* p) {
    uint32_t a;
    asm("{ .reg .u64 t; cvta.to.shared.u64 t, %1; cvt.u32.u64 %0, t; }"
        : "=r"(a) : "l"(p));
    return a;
}
__device__ __forceinline__ void cp_async16(uint32_t dst, const void* src) {
    asm volatile("cp.async.ca.shared.global [%0], [%1], 16;"
                 :: "r"(dst), "l"(src) : "memory");
}
__device__ __forceinline__ void cp_commit() {
    asm volatile("cp.async.commit_group;" ::: "memory");
}
template<int N> __device__ __forceinline__ void cp_wait() {
    asm volatile("cp.async.wait_group %0;" :: "n"(N) : "memory");
}
// m16n8k16 f16 MMA, A row-major, B col-major, f32 accumulate (in-place)
__device__ __forceinline__ void mma16(float* d,
                                      uint32_t a0, uint32_t a1, uint32_t a2, uint32_t a3,
                                      uint32_t b0, uint32_t b1) {
    asm volatile(
        "mma.sync.aligned.m16n8k16.row.col.f32.f16.f16.f32 "
        "{%0,%1,%2,%3},{%4,%5,%6,%7},{%8,%9},{%0,%1,%2,%3};"
        : "+f"(d[0]), "+f"(d[1]), "+f"(d[2]), "+f"(d[3])
        : "r"(a0), "r"(a1), "r"(a2), "r"(a3), "r"(b0), "r"(b1));
}

// ------------------------------ head conv (IC=3), NCHW in -> NHWC out -------
#define CTX 32
#define CTY 4
__global__ void conv_head(const float* __restrict__ x,
                          const float* __restrict__ w,
                          const float* __restrict__ bias,
                          float* __restrict__ out)
{
    __shared__ float in_s[3][CTY+2][CTX+2];
    __shared__ float w_s[3*9*16];
    const int tx = threadIdx.x, ty = threadIdx.y;
    const int tid = ty*CTX + tx;
    const int x0 = blockIdx.x*CTX, y0 = blockIdx.y*CTY;
    const int ocg0 = blockIdx.z*16;

    float acc[16];
#pragma unroll
    for (int i = 0; i < 16; i++) acc[i] = 0.f;

    const int tot = 3*(CTY+2)*(CTX+2);
    for (int i = tid; i < tot; i += CTX*CTY) {
        int ic  = i / ((CTY+2)*(CTX+2));
        int rem = i % ((CTY+2)*(CTX+2));
        int ly = rem / (CTX+2), lx = rem % (CTX+2);
        int gy = y0 - 1 + ly, gx = x0 - 1 + lx;
        float v = 0.f;
        if (gy >= 0 && gy < H && gx >= 0 && gx < W)
            v = x[(size_t)ic*HW + gy*W + gx];
        in_s[ic][ly][lx] = v;
    }
    for (int i = tid; i < 3*9*16; i += CTX*CTY) {
        int oc = i & 15;
        int t2 = i >> 4;
        int tap = t2 % 9, ic = t2 / 9;
        w_s[(ic*9+tap)*16 + oc] = w[(size_t)(ocg0+oc)*27 + ic*9 + tap];
    }
    __syncthreads();
    for (int ic = 0; ic < 3; ic++) {
#pragma unroll
        for (int tap = 0; tap < 9; tap++) {
            const int dy = tap/3, dx = tap%3;
            float a = in_s[ic][ty+dy][tx+dx];
            const float4* wp = (const float4*)&w_s[(ic*9+tap)*16];
            float wv[16];
            *(float4*)&wv[0]  = wp[0];
            *(float4*)&wv[4]  = wp[1];
            *(float4*)&wv[8]  = wp[2];
            *(float4*)&wv[12] = wp[3];
#pragma unroll
            for (int oc = 0; oc < 16; oc++)
                acc[oc] = fmaf(a, wv[oc], acc[oc]);
        }
    }
    const int pix = (y0+ty)*W + (x0+tx);
    float4* o4 = (float4*)(out + (size_t)pix*64 + ocg0);
#pragma unroll
    for (int v = 0; v < 4; v++) {
        float4 r;
        r.x = acc[v*4+0] + bias[ocg0+v*4+0];
        r.y = acc[v*4+1] + bias[ocg0+v*4+1];
        r.z = acc[v*4+2] + bias[ocg0+v*4+2];
        r.w = acc[v*4+3] + bias[ocg0+v*4+3];
        o4[v] = r;
    }
}

// ------------------------------ weight transforms (fp16) --------------------
// conv weights: [cv][tap(9)][n(64)][ic(64)] halfs
__global__ void prep_wch(const float* __restrict__ rb_w,
                         const float* __restrict__ tail_w,
                         __half* __restrict__ wt)
{
    int i = blockIdx.x*256 + threadIdx.x;       // < 33*36864
    int cv = i / 36864;
    int r  = i % 36864;
    int tap = r >> 12;
    int r2  = r & 4095;
    int n   = r2 >> 6;
    int ic  = r2 & 63;
    const float* src = (cv < 32) ? (rb_w + (size_t)cv*36864) : tail_w;
    wt[i] = __float2half(src[(size_t)n*576 + ic*9 + tap]);
}

__global__ void prep_wl0(const float* __restrict__ mw0,
                         __half* __restrict__ wl0)
{
    int i = blockIdx.x*256 + threadIdx.x;       // < 4*36864
    int grp = i / 36864;
    int r  = i % 36864;
    int tap = r >> 12;
    int r2  = r & 4095;
    int n   = r2 >> 6;
    int ic  = r2 & 63;
    int ng = grp*64 + n;
    wl0[i] = __float2half(mw0[(size_t)(ic*9 + tap)*256 + ng]);
}

// ------------------------------ implicit-GEMM 3x3 conv (fp16 tensor) --------
// CTA: 64 pixels (half image row) x 64 oc. 4 warps, each M32 x N32.
// MODE 0: out = relu(acc + bias)   (fp32 NHWC)
// MODE 1: out = acc + bias + res   (fp32 NHWC)
// MODE 2: outh = acc (fp16, [p][256], oc group = blockIdx.z)
#define SWD 36                        // strip words per pixel (32 + pad 4)
#define WRW 36                        // weight words per n-row
#define STRIP_WORDS (3*66*SWD)        // 7128
#define WBUF_WORDS (2*64*WRW)         // 4608
#define GSMEM ((STRIP_WORDS + WBUF_WORDS)*4)

template<int MODE>
__global__ void __launch_bounds__(128) conv_gemm(
    const float* __restrict__ in, const __half* __restrict__ wth,
    const float* __restrict__ bias, const float* __restrict__ res,
    float* __restrict__ out, __half* __restrict__ outh)
{
    extern __shared__ uint32_t sm[];
    uint32_t* strip = sm;
    uint32_t* wbuf  = sm + STRIP_WORDS;
    __shared__ float bias_s[64];

    const int tid = threadIdx.x, wid = tid >> 5, lane = tid & 31;
    const int g = lane >> 2, t = lane & 3;
    const int y = blockIdx.x >> 1, x0 = (blockIdx.x & 1)*64;
    const __half* wconv = (MODE == 2) ? wth + (size_t)blockIdx.z*36864 : wth;

    if (MODE != 2 && tid < 64) bias_s[tid] = bias[tid];

    // ---- prefetch tap 0 weights (64 rows x 64 halfs, 16B chunks)
    const uint32_t wbase = smem_u32(sm) + STRIP_WORDS*4;
#pragma unroll
    for (int ii = 0; ii < 4; ii++) {
        int i = tid + ii*128;           // 0..511
        int n = i >> 3, j = i & 7;
        cp_async16(wbase + (uint32_t)(n*WRW + j*4)*4, wconv + n*64 + j*8);
    }
    cp_commit();

    // ---- strip load: rows y-1..y+1, cols x0-1..x0+64, 64 ch -> half2 words
    const float4* in4 = (const float4*)in;
    for (int i = tid; i < 3168; i += 128) {
        int r = i / 1056, rem = i - r*1056;
        int j = rem >> 4, q = rem & 15;           // q = float4 index (ch 4q..4q+3)
        int gy = y - 1 + r, gx = x0 - 1 + j;
        uint32_t w0 = 0, w1 = 0;
        if (gy >= 0 && gy < H && gx >= 0 && gx < W) {
            float4 v = in4[(size_t)(gy*W + gx)*16 + q];
            __half2 h0 = __floats2half2_rn(v.x, v.y);
            __half2 h1 = __floats2half2_rn(v.z, v.w);
            w0 = *(const uint32_t*)&h0;
            w1 = *(const uint32_t*)&h1;
        }
        uint32_t base = (uint32_t)(r*66 + j)*SWD + 2*q;
        strip[base]     = w0;
        strip[base + 1] = w1;
    }

    float acc[2][4][4];
#pragma unroll
    for (int a = 0; a < 2; a++)
#pragma unroll
        for (int b = 0; b < 4; b++)
#pragma unroll
            for (int c = 0; c < 4; c++) acc[a][b][c] = 0.f;

    const int m0 = (wid & 1)*32, n0 = (wid >> 1)*32;

    for (int tap = 0; tap < 9; tap++) {
        if (tap < 8) {
            uint32_t db = wbase + ((tap + 1) & 1)*(64*WRW)*4u;
            const __half* src = wconv + (size_t)(tap + 1)*4096;
#pragma unroll
            for (int ii = 0; ii < 4; ii++) {
                int i = tid + ii*128;
                int n = i >> 3, j = i & 7;
                cp_async16(db + (uint32_t)(n*WRW + j*4)*4, src + n*64 + j*8);
            }
            cp_commit();
            cp_wait<1>();
        } else {
            cp_wait<0>();
        }
        __syncthreads();

        const uint32_t* wb = wbuf + (tap & 1)*(64*WRW);
        const int dy = tap/3, dx = tap%3;
        const uint32_t* arow0 = strip + (uint32_t)(dy*66 + dx)*SWD;
#pragma unroll
        for (int ks = 0; ks < 4; ks++) {
            const int kw = ks*8 + t;
            uint32_t af[2][4];
#pragma unroll
            for (int mt = 0; mt < 2; mt++) {
                const uint32_t* ar = arow0 + (uint32_t)(m0 + mt*16 + g)*SWD + kw;
                af[mt][0] = ar[0];
                af[mt][1] = ar[8*SWD];
                af[mt][2] = ar[4];
                af[mt][3] = ar[8*SWD + 4];
            }
#pragma unroll
            for (int nt = 0; nt < 4; nt++) {
                const uint32_t* bw = wb + (uint32_t)(n0 + nt*8 + g)*WRW + kw;
                uint32_t b0 = bw[0], b1 = bw[4];
                mma16(acc[0][nt], af[0][0], af[0][1], af[0][2], af[0][3], b0, b1);
                mma16(acc[1][nt], af[1][0], af[1][1], af[1][2], af[1][3], b0, b1);
            }
        }
        __syncthreads();
    }

    // ---- epilogue
    const int pix0 = y*W + x0;
#pragma unroll
    for (int mt = 0; mt < 2; mt++) {
        const int pr = pix0 + m0 + mt*16 + g;
#pragma unroll
        for (int nt = 0; nt < 4; nt++) {
            const int c0 = n0 + nt*8 + 2*t;
            float v0 = acc[mt][nt][0], v1 = acc[mt][nt][1];
            float v2 = acc[mt][nt][2], v3 = acc[mt][nt][3];
            if (MODE == 0) {
                float b0 = bias_s[c0], b1 = bias_s[c0+1];
                v0 = fmaxf(v0 + b0, 0.f); v1 = fmaxf(v1 + b1, 0.f);
                v2 = fmaxf(v2 + b0, 0.f); v3 = fmaxf(v3 + b1, 0.f);
            } else if (MODE == 1) {
                float b0 = bias_s[c0], b1 = bias_s[c0+1];
                float2 r0 = *(const float2*)(res + (size_t)pr*64 + c0);
                float2 r1 = *(const float2*)(res + (size_t)(pr+8)*64 + c0);
                v0 += b0 + r0.x; v1 += b1 + r0.y;
                v2 += b0 + r1.x; v3 += b1 + r1.y;
            }
            if (MODE != 2) {
                float2 s0 = {v0, v1}, s1 = {v2, v3};
                *(float2*)(out + (size_t)pr*64 + c0) = s0;
                *(float2*)(out + (size_t)(pr+8)*64 + c0) = s1;
            } else {
                const int cc = blockIdx.z*64 + c0;
                __half2 h0 = __floats2half2_rn(v0, v1);
                __half2 h1 = __floats2half2_rn(v2, v3);
                *(__half2*)(outh + (size_t)pr*256 + cc) = h0;
                *(__half2*)(outh + (size_t)(pr+8)*256 + cc) = h1;
            }
        }
    }
}

// ---- prep: fold q_cell into bias ------------------------------------------
__global__ void prep_kernel(const float* __restrict__ mw0,
                            const float* __restrict__ mb0,
                            float* __restrict__ b0eff)
{
    int o = threadIdx.x;
    b0eff[o] = mb0[o] + 0.5f*mw0[578*256 + o] + 0.5f*mw0[579*256 + o];
}

// ---- transpose + fp16 for the 3 MLP hidden weights: w[K][N] -> wh[N][K] ----
__global__ void w_fp16_kernel(const float* __restrict__ w1,
                              const float* __restrict__ w2,
                              const float* __restrict__ w3,
                              __half* __restrict__ wh1,
                              __half* __restrict__ wh2,
                              __half* __restrict__ wh3)
{
    int gi = blockIdx.x*256 + threadIdx.x;   // < 3*65536
    int which = gi >> 16;
    int idx = gi & 65535;
    int n = idx >> 8, k = idx & 255;
    const float* w = (which == 0) ? w1 : (which == 1) ? w2 : w3;
    __half* wh = (which == 0) ? wh1 : (which == 1) ? wh2 : wh3;
    wh[idx] = __float2half(w[k*256 + n]);
}

// ------------------------------ LIIF query + mma.sync fp16 MLP --------------
#define QB 32
#define SB 128
#define QTHREADS 256
#define ASH 264
#define WSH 72
#define OFF_ACT 0
#define OFF_WB0 67584
#define OFF_WB1 104448
#define OFF_BIAS 141312
#define DYN_BYTES 142336

__device__ __forceinline__ void load_wchunk(uint32_t dst_base,
                                            const __half* __restrict__ Wg,
                                            int c, int tid)
{
#pragma unroll
    for (int ii = 0; ii < 8; ii++) {
        int i = tid + ii*QTHREADS;
        int n = i >> 3, j = i & 7;
        cp_async16(dst_base + (uint32_t)(n*(WSH*2) + j*16),
                   Wg + (size_t)n*256 + c*64 + j*8);
    }
}

__global__ __launch_bounds__(QTHREADS)
void query_kernel(const __half* __restrict__ G,
                  const float* __restrict__ mw0,
                  const float* __restrict__ b0eff,
                  const __half* __restrict__ w1h, const float* __restrict__ b1,
                  const __half* __restrict__ w2h, const float* __restrict__ b2,
                  const __half* __restrict__ w3h, const float* __restrict__ b3,
                  const float* __restrict__ w4, const float* __restrict__ b4,
                  float* __restrict__ out)
{
    extern __shared__ char dyn[];
    uint32_t* actu = (uint32_t*)(dyn + OFF_ACT);
    __half*   acth = (__half*)(dyn + OFF_ACT);
    float*    bias_s = (float*)(dyn + OFF_BIAS);
    __shared__ int   p_s[SB];
    __shared__ float relh_s[SB], relw_s[SB], area_s[SB];
    __shared__ float pred_s[SB][4];

    const int tid  = threadIdx.x;
    const int wid  = tid >> 5;
    const int lane = tid & 31;
    const int g    = lane >> 2;
    const int t    = lane & 3;

    const uint32_t dynaddr = smem_u32(dyn);
    const uint32_t wbaddr[2] = {dynaddr + OFF_WB0, dynaddr + OFF_WB1};
    const uint32_t* wbuf[2] = {(const uint32_t*)(dyn + OFF_WB0),
                               (const uint32_t*)(dyn + OFF_WB1)};

    if (tid < SB) {
        int m  = tid;
        int q  = blockIdx.x*QB + (m >> 2);
        int oh = q >> 9, ow = q & 511;
        int r  = (m >> 1) & 1, c = m & 1;
        float sh = (oh + 0.5f)*(2.0f/512.0f) - 1.0f;
        float sw = (ow + 0.5f)*(2.0f/512.0f) - 1.0f;
        const float d = 1.0f/128.0f, EPS = 1e-6f;
        float gh = fminf(fmaxf(sh + (2.f*r - 1.f)*d, -1.f + EPS), 1.f - EPS);
        float gw = fminf(fmaxf(sw + (2.f*c - 1.f)*d, -1.f + EPS), 1.f - EPS);
        float fy = ((gh + 1.0f)*128.0f - 1.0f)*0.5f;
        float fx = ((gw + 1.0f)*128.0f - 1.0f)*0.5f;
        int iy = min(max((int)rintf(fy), 0), 127);
        int ix = min(max((int)rintf(fx), 0), 127);
        float qgh = (iy + 0.5f)*(2.0f/128.0f) - 1.0f;
        float qgw = (ix + 0.5f)*(2.0f/128.0f) - 1.0f;
        float rh = (sh - qgh)*128.0f;
        float rw = (sw - qgw)*128.0f;
        p_s[m] = iy*128 + ix;
        relh_s[m] = rh; relw_s[m] = rw;
        area_s[m] = fabsf(rh*rw);
    }

    load_wchunk(wbaddr[0], w1h, 0, tid);
    cp_commit();
    __syncthreads();

    {
        const int ocw = tid & 127;
        const int oc0 = ocw*2;
        float u0 = mw0[576*256 + oc0],     u1 = mw0[576*256 + oc0 + 1];
        float v0 = mw0[577*256 + oc0],     v1 = mw0[577*256 + oc0 + 1];
        float b0v = b0eff[oc0],            b1v = b0eff[oc0 + 1];
        const __half2* G2 = (const __half2*)G;
        for (int m = (tid >> 7); m < SB; m += 2) {
            __half2 gg = G2[(size_t)p_s[m]*128 + ocw];
            float rh = relh_s[m], rw = relw_s[m];
            float x0v = fmaf(rh, u0, fmaf(rw, v0, __low2float(gg)  + b0v));
            float x1v = fmaf(rh, u1, fmaf(rw, v1, __high2float(gg) + b1v));
            __half2 hv = __floats2half2_rn(fmaxf(x0v, 0.f), fmaxf(x1v, 0.f));
            actu[m*(ASH/2) + ocw] = *(const uint32_t*)&hv;
        }
    }
    __syncthreads();

    const int m0  = (wid & 3)*32;
    const int n0b = (wid >> 2)*128;

    const __half* Ws[3] = {w1h, w2h, w3h};
    const float*  Bs[3] = {b1, b2, b3};

    int cnt = 0;
    for (int L = 0; L < 3; L++) {
        bias_s[tid] = Bs[L][tid];

        float acc[2][16][4];
#pragma unroll
        for (int mt = 0; mt < 2; mt++)
#pragma unroll
            for (int nt = 0; nt < 16; nt++)
#pragma unroll
                for (int i = 0; i < 4; i++) acc[mt][nt][i] = 0.f;

        for (int c = 0; c < 4; c++) {
            const bool has_next = (c < 3) || (L < 2);
            if (has_next) {
                const __half* Wn = (c < 3) ? Ws[L] : Ws[L+1];
                const int cn = (c < 3) ? c + 1 : 0;
                load_wchunk(wbaddr[(cnt + 1) & 1], Wn, cn, tid);
                cp_commit();
                cp_wait<1>();
            } else {
                cp_wait<0>();
            }
            __syncthreads();

            const uint32_t* wb = wbuf[cnt & 1];
#pragma unroll
            for (int ks = 0; ks < 4; ks++) {
                const int kw = c*32 + ks*8;
                uint32_t af[2][4];
#pragma unroll
                for (int mt = 0; mt < 2; mt++) {
                    const uint32_t* ar = actu + (m0 + mt*16 + g)*(ASH/2) + kw + t;
                    af[mt][0] = ar[0];
                    af[mt][2] = ar[4];
                    af[mt][1] = ar[8*(ASH/2)];
                    af[mt][3] = ar[8*(ASH/2) + 4];
                }
                const uint32_t* wp = wb + (size_t)(n0b + g)*(WSH/2) + ks*8 + t;
#pragma unroll
                for (int nt = 0; nt < 16; nt++) {
                    uint32_t b0 = wp[nt*8*(WSH/2)];
                    uint32_t b1r = wp[nt*8*(WSH/2) + 4];
                    mma16(acc[0][nt], af[0][0], af[0][1], af[0][2], af[0][3], b0, b1r);
                    mma16(acc[1][nt], af[1][0], af[1][1], af[1][2], af[1][3], b0, b1r);
                }
            }
            cnt++;
            __syncthreads();
        }

#pragma unroll
        for (int mt = 0; mt < 2; mt++) {
            const int r0 = m0 + mt*16 + g;
#pragma unroll
            for (int nt = 0; nt < 16; nt++) {
                const int col = n0b + nt*8 + 2*t;
                float v0 = fmaxf(acc[mt][nt][0] + bias_s[col],     0.f);
                float v1 = fmaxf(acc[mt][nt][1] + bias_s[col + 1], 0.f);
                float v2 = fmaxf(acc[mt][nt][2] + bias_s[col],     0.f);
                float v3 = fmaxf(acc[mt][nt][3] + bias_s[col + 1], 0.f);
                __half2 h01 = __floats2half2_rn(v0, v1);
                __half2 h23 = __floats2half2_rn(v2, v3);
                const int cw = (n0b >> 1) + nt*4 + t;
                actu[r0*(ASH/2) + cw]     = *(const uint32_t*)&h01;
                actu[(r0+8)*(ASH/2) + cw] = *(const uint32_t*)&h23;
            }
        }
        __syncthreads();
    }

    {
        float* wsm = (float*)(dyn + OFF_WB0);
        for (int i = tid; i < 768; i += QTHREADS) wsm[i] = w4[i];
        __syncthreads();
        if (tid < SB) {
            const __half* ap = acth + tid*ASH;
            float s0 = b4[0], s1 = b4[1], s2 = b4[2];
#pragma unroll 4
            for (int k = 0; k < 256; k++) {
                float a = __half2float(ap[k]);
                s0 = fmaf(a, wsm[k*3 + 0], s0);
                s1 = fmaf(a, wsm[k*3 + 1], s1);
                s2 = fmaf(a, wsm[k*3 + 2], s2);
            }
            pred_s[tid][0] = s0; pred_s[tid][1] = s1; pred_s[tid][2] = s2;
        }
    }
    __syncthreads();

    if (tid < QB) {
        int bb = tid*4;
        float a0 = area_s[bb+0], a1 = area_s[bb+1];
        float a2 = area_s[bb+2], a3 = area_s[bb+3];
        float tot = a0 + a1 + a2 + a3 + 1e-9f;
        int q = blockIdx.x*QB + tid;
#pragma unroll
        for (int j = 0; j < 3; j++) {
            float num = pred_s[bb+0][j]*a3 + pred_s[bb+1][j]*a2
                      + pred_s[bb+2][j]*a1 + pred_s[bb+3][j]*a0;
            float yv = num / tot;
            yv = fminf(fmaxf(yv, 0.f), 1.f);
            out[(size_t)j*NQ + q] = yv;
        }
    }
}

// ------------------------------ launch --------------------------------------
extern "C" void kernel_launch(void* const* d_in, const int* in_sizes, int n_in,
                              void* d_out, int out_size)
{
    const float* x      = (const float*)d_in[0];
    const float* head_w = (const float*)d_in[2];
    const float* head_b = (const float*)d_in[3];
    const float* rb_w   = (const float*)d_in[4];
    const float* rb_b   = (const float*)d_in[5];
    const float* tail_w = (const float*)d_in[6];
    const float* tail_b = (const float*)d_in[7];
    const float* mw0 = (const float*)d_in[8];
    const float* mb0 = (const float*)d_in[9];
    const float* mw1 = (const float*)d_in[10];
    const float* mb1 = (const float*)d_in[11];
    const float* mw2 = (const float*)d_in[12];
    const float* mb2 = (const float*)d_in[13];
    const float* mw3 = (const float*)d_in[14];
    const float* mb3 = (const float*)d_in[15];
    const float* mw4 = (const float*)d_in[16];
    const float* mb4 = (const float*)d_in[17];
    float* out = (float*)d_out;

    float *h0, *A, *B, *C, *b0eff;
    __half *G, *w1h, *w2h, *w3h, *wch, *wl0;
    cudaGetSymbolAddress((void**)&h0, g_h0);
    cudaGetSymbolAddress((void**)&A,  g_A);
    cudaGetSymbolAddress((void**)&B,  g_B);
    cudaGetSymbolAddress((void**)&C,  g_C);
    cudaGetSymbolAddress((void**)&G,  g_G);
    cudaGetSymbolAddress((void**)&b0eff, g_b0eff);
    cudaGetSymbolAddress((void**)&w1h, g_w1h);
    cudaGetSymbolAddress((void**)&w2h, g_w2h);
    cudaGetSymbolAddress((void**)&w3h, g_w3h);
    cudaGetSymbolAddress((void**)&wch, g_wch);
    cudaGetSymbolAddress((void**)&wl0, g_wl0);

    // weight transforms
    prep_wch<<<(33*36864)/256, 256>>>(rb_w, tail_w, wch);
    prep_wl0<<<(4*36864)/256, 256>>>(mw0, wl0);
    prep_kernel<<<1, 256>>>(mw0, mb0, b0eff);
    w_fp16_kernel<<<768, 256>>>(mw1, mw2, mw3, w1h, w2h, w3h);

    cudaFuncSetAttribute(conv_gemm<0>, cudaFuncAttributeMaxDynamicSharedMemorySize, GSMEM);
    cudaFuncSetAttribute(conv_gemm<1>, cudaFuncAttributeMaxDynamicSharedMemorySize, GSMEM);
    cudaFuncSetAttribute(conv_gemm<2>, cudaFuncAttributeMaxDynamicSharedMemorySize, GSMEM);

    // head conv -> NHWC h0
    conv_head<<<dim3(W/CTX, H/CTY, 4), dim3(CTX, CTY)>>>(x, head_w, head_b, h0);

    // 16 resblocks (NHWC, fp16 tensor)
    const float* hcur = h0;
    float* pp[2] = {A, C};
    for (int i = 0; i < 16; i++) {
        conv_gemm<0><<<256, 128, GSMEM>>>(hcur, wch + (size_t)(2*i)*36864,
                                          rb_b + 2*i*64, nullptr, B, nullptr);
        float* ho = pp[i & 1];
        conv_gemm<1><<<256, 128, GSMEM>>>(B, wch + (size_t)(2*i+1)*36864,
                                          rb_b + (2*i+1)*64, hcur, ho, nullptr);
        hcur = ho;
    }
    // tail conv + global residual -> feat in B
    conv_gemm<1><<<256, 128, GSMEM>>>(hcur, wch + (size_t)32*36864,
                                      tail_b, h0, B, nullptr);

    // layer-0-as-conv: G[16384][256] fp16
    conv_gemm<2><<<dim3(256, 1, 4), 128, GSMEM>>>(B, wl0, nullptr, nullptr,
                                                  nullptr, G);

    cudaFuncSetAttribute(query_kernel,
                         cudaFuncAttributeMaxDynamicSharedMemorySize,
                         DYN_BYTES);
    query_kernel<<<NQ/QB, QTHREADS, DYN_BYTES>>>(
        G, mw0, b0eff, w1h, mb1, w2h, mb2, w3h, mb3, mw4, mb4, out);
}

// round 7
// speedup vs baseline: 6.2594x; 1.0241x over previous
#include <cuda_runtime.h>
#include <cuda_fp16.h>
#include <cstdint>

#define H 128
#define W 128
#define HW 16384
#define OH 512
#define OWID 512
#define NQ (OH*OWID)

// ------------------------------ scratch (device globals, no allocation) ----
__device__ __align__(16) float g_h0[64*HW];      // fp32 NHWC (residual chain)
__device__ __align__(16) float g_A [64*HW];
__device__ __align__(16) float g_C [64*HW];
__device__ __align__(16) __half g_h0h[64*HW];    // fp16 NHWC (conv inputs)
__device__ __align__(16) __half g_Ah [64*HW];
__device__ __align__(16) __half g_Bh [64*HW];
__device__ __align__(16) __half g_Ch [64*HW];
__device__ __align__(16) __half g_G [(size_t)HW*256];
__device__ float g_b0eff[256];
__device__ __align__(16) __half g_w1h[65536];    // fp16 MLP weights, [N][K]
__device__ __align__(16) __half g_w2h[65536];
__device__ __align__(16) __half g_w3h[65536];
__device__ __align__(16) __half g_wch[33*36864]; // fp16 conv weights [cv][tap][n][ic]
__device__ __align__(16) __half g_wl0[4*36864];  // fp16 layer-0 conv weights

// ------------------------------ PTX helpers --------------------------------
__device__ __forceinline__ uint32_t smem_u32(const void* p) {
    uint32_t a;
    asm("{ .reg .u64 t; cvta.to.shared.u64 t, %1; cvt.u32.u64 %0, t; }"
        : "=r"(a) : "l"(p));
    return a;
}
__device__ __forceinline__ void cp_async16(uint32_t dst, const void* src) {
    asm volatile("cp.async.ca.shared.global [%0], [%1], 16;"
                 :: "r"(dst), "l"(src) : "memory");
}
__device__ __forceinline__ void cp_commit() {
    asm volatile("cp.async.commit_group;" ::: "memory");
}
template<int N> __device__ __forceinline__ void cp_wait() {
    asm volatile("cp.async.wait_group %0;" :: "n"(N) : "memory");
}
// m16n8k16 f16 MMA, A row-major, B col-major, f32 accumulate (in-place)
__device__ __forceinline__ void mma16(float* d,
                                      uint32_t a0, uint32_t a1, uint32_t a2, uint32_t a3,
                                      uint32_t b0, uint32_t b1) {
    asm volatile(
        "mma.sync.aligned.m16n8k16.row.col.f32.f16.f16.f32 "
        "{%0,%1,%2,%3},{%4,%5,%6,%7},{%8,%9},{%0,%1,%2,%3};"
        : "+f"(d[0]), "+f"(d[1]), "+f"(d[2]), "+f"(d[3])
        : "r"(a0), "r"(a1), "r"(a2), "r"(a3), "r"(b0), "r"(b1));
}

// ------------------------------ head conv (IC=3), NCHW in -> NHWC out -------
#define CTX 32
#define CTY 4
__global__ void conv_head(const float* __restrict__ x,
                          const float* __restrict__ w,
                          const float* __restrict__ bias,
                          float* __restrict__ out,
                          __half* __restrict__ outh)
{
    __shared__ float in_s[3][CTY+2][CTX+2];
    __shared__ float w_s[3*9*16];
    const int tx = threadIdx.x, ty = threadIdx.y;
    const int tid = ty*CTX + tx;
    const int x0 = blockIdx.x*CTX, y0 = blockIdx.y*CTY;
    const int ocg0 = blockIdx.z*16;

    float acc[16];
#pragma unroll
    for (int i = 0; i < 16; i++) acc[i] = 0.f;

    const int tot = 3*(CTY+2)*(CTX+2);
    for (int i = tid; i < tot; i += CTX*CTY) {
        int ic  = i / ((CTY+2)*(CTX+2));
        int rem = i % ((CTY+2)*(CTX+2));
        int ly = rem / (CTX+2), lx = rem % (CTX+2);
        int gy = y0 - 1 + ly, gx = x0 - 1 + lx;
        float v = 0.f;
        if (gy >= 0 && gy < H && gx >= 0 && gx < W)
            v = x[(size_t)ic*HW + gy*W + gx];
        in_s[ic][ly][lx] = v;
    }
    for (int i = tid; i < 3*9*16; i += CTX*CTY) {
        int oc = i & 15;
        int t2 = i >> 4;
        int tap = t2 % 9, ic = t2 / 9;
        w_s[(ic*9+tap)*16 + oc] = w[(size_t)(ocg0+oc)*27 + ic*9 + tap];
    }
    __syncthreads();
    for (int ic = 0; ic < 3; ic++) {
#pragma unroll
        for (int tap = 0; tap < 9; tap++) {
            const int dy = tap/3, dx = tap%3;
            float a = in_s[ic][ty+dy][tx+dx];
            const float4* wp = (const float4*)&w_s[(ic*9+tap)*16];
            float wv[16];
            *(float4*)&wv[0]  = wp[0];
            *(float4*)&wv[4]  = wp[1];
            *(float4*)&wv[8]  = wp[2];
            *(float4*)&wv[12] = wp[3];
#pragma unroll
            for (int oc = 0; oc < 16; oc++)
                acc[oc] = fmaf(a, wv[oc], acc[oc]);
        }
    }
    const int pix = (y0+ty)*W + (x0+tx);
    float4* o4 = (float4*)(out + (size_t)pix*64 + ocg0);
    __half2* oh2 = (__half2*)(outh + (size_t)pix*64 + ocg0);
#pragma unroll
    for (int v = 0; v < 4; v++) {
        float4 r;
        r.x = acc[v*4+0] + bias[ocg0+v*4+0];
        r.y = acc[v*4+1] + bias[ocg0+v*4+1];
        r.z = acc[v*4+2] + bias[ocg0+v*4+2];
        r.w = acc[v*4+3] + bias[ocg0+v*4+3];
        o4[v] = r;
        oh2[v*2]   = __floats2half2_rn(r.x, r.y);
        oh2[v*2+1] = __floats2half2_rn(r.z, r.w);
    }
}

// ------------------------------ weight transforms (fp16) --------------------
// conv weights: [cv][tap(9)][n(64)][ic(64)] halfs
__global__ void prep_wch(const float* __restrict__ rb_w,
                         const float* __restrict__ tail_w,
                         __half* __restrict__ wt)
{
    int i = blockIdx.x*256 + threadIdx.x;       // < 33*36864
    int cv = i / 36864;
    int r  = i % 36864;
    int tap = r >> 12;
    int r2  = r & 4095;
    int n   = r2 >> 6;
    int ic  = r2 & 63;
    const float* src = (cv < 32) ? (rb_w + (size_t)cv*36864) : tail_w;
    wt[i] = __float2half(src[(size_t)n*576 + ic*9 + tap]);
}

__global__ void prep_wl0(const float* __restrict__ mw0,
                         __half* __restrict__ wl0)
{
    int i = blockIdx.x*256 + threadIdx.x;       // < 4*36864
    int grp = i / 36864;
    int r  = i % 36864;
    int tap = r >> 12;
    int r2  = r & 4095;
    int n   = r2 >> 6;
    int ic  = r2 & 63;
    int ng = grp*64 + n;
    wl0[i] = __float2half(mw0[(size_t)(ic*9 + tap)*256 + ng]);
}

// ------------------------------ implicit-GEMM 3x3 conv (fp16 tensor) --------
// CTA: one image row (128 px) x 64 oc. 256 threads, 8 warps (4M x 2N),
// each warp M32 x N32. All weights (9 taps) + 3-row strip staged up front.
// MODE 0: outh = relu(acc + bias)            (fp16)
// MODE 1: out  = acc + bias + res (fp32, optional), outh same value (fp16)
// MODE 2: outh = acc (fp16, [p][256], oc group = blockIdx.z)
#define PXW 36                          // words per pixel slot (32 + pad 4)
#define STRIPW2 (3*130*PXW)             // 14040 words
#define WTW (9*64*PXW)                  // 20736 words
#define GSMEM2 ((STRIPW2 + WTW)*4)      // 139104 bytes

template<int MODE>
__global__ void __launch_bounds__(256) conv_gemm(
    const __half* __restrict__ inh, const __half* __restrict__ wth,
    const float* __restrict__ bias, const float* __restrict__ res,
    float* __restrict__ out, __half* __restrict__ outh)
{
    extern __shared__ uint32_t sm[];
    uint32_t* strip = sm;
    uint32_t* wsm   = sm + STRIPW2;
    __shared__ float bias_s[64];

    const int tid = threadIdx.x, wid = tid >> 5, lane = tid & 31;
    const int g = lane >> 2, t = lane & 3;
    const int y = blockIdx.x;
    const __half* wconv = (MODE == 2) ? wth + (size_t)blockIdx.z*36864 : wth;

    if (MODE != 2 && tid < 64) bias_s[tid] = bias[tid];

    const uint32_t smaddr = smem_u32(sm);
    const uint32_t wbase = smaddr + STRIPW2*4;

    // ---- all 9 taps of weights: 4608 x 16B cp.async
#pragma unroll
    for (int ii = 0; ii < 18; ii++) {
        int i = tid + ii*256;            // 0..4607
        int n2 = i >> 3, j = i & 7;      // n2 = tap*64 + n
        cp_async16(wbase + (uint32_t)(n2*PXW + j*4)*4, wconv + n2*64 + j*8);
    }

    // ---- zero strip (halo), then barrier, then strip cp.async
    {
        uint4 z = {0, 0, 0, 0};
        uint4* s4 = (uint4*)sm;
        for (int i = tid; i < STRIPW2/4; i += 256) s4[i] = z;
    }
    __syncthreads();

    for (int i = tid; i < 3120; i += 256) {
        int r = i / 1040, rem = i - r*1040;
        int j = rem >> 3, c = rem & 7;
        int gy = y - 1 + r, gx = j - 1;
        if (gy >= 0 && gy < H && gx >= 0 && gx < W)
            cp_async16(smaddr + (uint32_t)((r*130 + j)*PXW + c*4)*4,
                       inh + ((size_t)(gy*W + gx))*64 + c*8);
    }
    cp_commit();
    cp_wait<0>();
    __syncthreads();

    float acc[2][4][4];
#pragma unroll
    for (int a = 0; a < 2; a++)
#pragma unroll
        for (int b = 0; b < 4; b++)
#pragma unroll
            for (int c = 0; c < 4; c++) acc[a][b][c] = 0.f;

    const int m0 = (wid & 3)*32, n0 = (wid >> 2)*32;

    for (int tap = 0; tap < 9; tap++) {
        const int dy = tap/3, dx = tap%3;
        const uint32_t* wb = wsm + tap*(64*PXW);
        const uint32_t* arow0 = strip + (uint32_t)(dy*130 + dx)*PXW;
#pragma unroll
        for (int ks = 0; ks < 4; ks++) {
            const int kw = ks*8 + t;
            uint32_t af[2][4];
#pragma unroll
            for (int mt = 0; mt < 2; mt++) {
                const uint32_t* ar = arow0 + (uint32_t)(m0 + mt*16 + g)*PXW + kw;
                af[mt][0] = ar[0];
                af[mt][1] = ar[8*PXW];
                af[mt][2] = ar[4];
                af[mt][3] = ar[8*PXW + 4];
            }
#pragma unroll
            for (int nt = 0; nt < 4; nt++) {
                const uint32_t* bw = wb + (uint32_t)(n0 + nt*8 + g)*PXW + kw;
                uint32_t b0 = bw[0], b1 = bw[4];
                mma16(acc[0][nt], af[0][0], af[0][1], af[0][2], af[0][3], b0, b1);
                mma16(acc[1][nt], af[1][0], af[1][1], af[1][2], af[1][3], b0, b1);
            }
        }
    }

    // ---- epilogue
    const int pix0 = y*W;
#pragma unroll
    for (int mt = 0; mt < 2; mt++) {
        const int pr = pix0 + m0 + mt*16 + g;
#pragma unroll
        for (int nt = 0; nt < 4; nt++) {
            const int c0 = n0 + nt*8 + 2*t;
            float v0 = acc[mt][nt][0], v1 = acc[mt][nt][1];
            float v2 = acc[mt][nt][2], v3 = acc[mt][nt][3];
            if (MODE == 0) {
                float b0 = bias_s[c0], b1 = bias_s[c0+1];
                v0 = fmaxf(v0 + b0, 0.f); v1 = fmaxf(v1 + b1, 0.f);
                v2 = fmaxf(v2 + b0, 0.f); v3 = fmaxf(v3 + b1, 0.f);
            } else if (MODE == 1) {
                float b0 = bias_s[c0], b1 = bias_s[c0+1];
                float2 r0 = *(const float2*)(res + (size_t)pr*64 + c0);
                float2 r1 = *(const float2*)(res + (size_t)(pr+8)*64 + c0);
                v0 += b0 + r0.x; v1 += b1 + r0.y;
                v2 += b0 + r1.x; v3 += b1 + r1.y;
            }
            if (MODE == 1 && out) {
                float2 s0 = {v0, v1}, s1 = {v2, v3};
                *(float2*)(out + (size_t)pr*64 + c0) = s0;
                *(float2*)(out + (size_t)(pr+8)*64 + c0) = s1;
            }
            __half2 h0 = __floats2half2_rn(v0, v1);
            __half2 h1 = __floats2half2_rn(v2, v3);
            if (MODE != 2) {
                *(__half2*)(outh + (size_t)pr*64 + c0) = h0;
                *(__half2*)(outh + (size_t)(pr+8)*64 + c0) = h1;
            } else {
                const int cc = blockIdx.z*64 + c0;
                *(__half2*)(outh + (size_t)pr*256 + cc) = h0;
                *(__half2*)(outh + (size_t)(pr+8)*256 + cc) = h1;
            }
        }
    }
}

// ---- prep: fold q_cell into bias ------------------------------------------
__global__ void prep_kernel(const float* __restrict__ mw0,
                            const float* __restrict__ mb0,
                            float* __restrict__ b0eff)
{
    int o = threadIdx.x;
    b0eff[o] = mb0[o] + 0.5f*mw0[578*256 + o] + 0.5f*mw0[579*256 + o];
}

// ---- transpose + fp16 for the 3 MLP hidden weights: w[K][N] -> wh[N][K] ----
__global__ void w_fp16_kernel(const float* __restrict__ w1,
                              const float* __restrict__ w2,
                              const float* __restrict__ w3,
                              __half* __restrict__ wh1,
                              __half* __restrict__ wh2,
                              __half* __restrict__ wh3)
{
    int gi = blockIdx.x*256 + threadIdx.x;   // < 3*65536
    int which = gi >> 16;
    int idx = gi & 65535;
    int n = idx >> 8, k = idx & 255;
    const float* w = (which == 0) ? w1 : (which == 1) ? w2 : w3;
    __half* wh = (which == 0) ? wh1 : (which == 1) ? wh2 : wh3;
    wh[idx] = __float2half(w[k*256 + n]);
}

// ------------------------------ LIIF query + mma.sync fp16 MLP --------------
#define QB 32
#define SB 128
#define QTHREADS 256
#define ASH 264
#define WSH 72
#define OFF_ACT 0
#define OFF_WB0 67584
#define OFF_WB1 104448
#define OFF_BIAS 141312
#define DYN_BYTES 142336

__device__ __forceinline__ void load_wchunk(uint32_t dst_base,
                                            const __half* __restrict__ Wg,
                                            int c, int tid)
{
#pragma unroll
    for (int ii = 0; ii < 8; ii++) {
        int i = tid + ii*QTHREADS;
        int n = i >> 3, j = i & 7;
        cp_async16(dst_base + (uint32_t)(n*(WSH*2) + j*16),
                   Wg + (size_t)n*256 + c*64 + j*8);
    }
}

__global__ __launch_bounds__(QTHREADS)
void query_kernel(const __half* __restrict__ G,
                  const float* __restrict__ mw0,
                  const float* __restrict__ b0eff,
                  const __half* __restrict__ w1h, const float* __restrict__ b1,
                  const __half* __restrict__ w2h, const float* __restrict__ b2,
                  const __half* __restrict__ w3h, const float* __restrict__ b3,
                  const float* __restrict__ w4, const float* __restrict__ b4,
                  float* __restrict__ out)
{
    extern __shared__ char dyn[];
    uint32_t* actu = (uint32_t*)(dyn + OFF_ACT);
    __half*   acth = (__half*)(dyn + OFF_ACT);
    float*    bias_s = (float*)(dyn + OFF_BIAS);
    __shared__ int   p_s[SB];
    __shared__ float relh_s[SB], relw_s[SB], area_s[SB];
    __shared__ float pred_s[SB][4];

    const int tid  = threadIdx.x;
    const int wid  = tid >> 5;
    const int lane = tid & 31;
    const int g    = lane >> 2;
    const int t    = lane & 3;

    const uint32_t dynaddr = smem_u32(dyn);
    const uint32_t wbaddr[2] = {dynaddr + OFF_WB0, dynaddr + OFF_WB1};
    const uint32_t* wbuf[2] = {(const uint32_t*)(dyn + OFF_WB0),
                               (const uint32_t*)(dyn + OFF_WB1)};

    if (tid < SB) {
        int m  = tid;
        int q  = blockIdx.x*QB + (m >> 2);
        int oh = q >> 9, ow = q & 511;
        int r  = (m >> 1) & 1, c = m & 1;
        float sh = (oh + 0.5f)*(2.0f/512.0f) - 1.0f;
        float sw = (ow + 0.5f)*(2.0f/512.0f) - 1.0f;
        const float d = 1.0f/128.0f, EPS = 1e-6f;
        float gh = fminf(fmaxf(sh + (2.f*r - 1.f)*d, -1.f + EPS), 1.f - EPS);
        float gw = fminf(fmaxf(sw + (2.f*c - 1.f)*d, -1.f + EPS), 1.f - EPS);
        float fy = ((gh + 1.0f)*128.0f - 1.0f)*0.5f;
        float fx = ((gw + 1.0f)*128.0f - 1.0f)*0.5f;
        int iy = min(max((int)rintf(fy), 0), 127);
        int ix = min(max((int)rintf(fx), 0), 127);
        float qgh = (iy + 0.5f)*(2.0f/128.0f) - 1.0f;
        float qgw = (ix + 0.5f)*(2.0f/128.0f) - 1.0f;
        float rh = (sh - qgh)*128.0f;
        float rw = (sw - qgw)*128.0f;
        p_s[m] = iy*128 + ix;
        relh_s[m] = rh; relw_s[m] = rw;
        area_s[m] = fabsf(rh*rw);
    }

    load_wchunk(wbaddr[0], w1h, 0, tid);
    cp_commit();
    __syncthreads();

    {
        const int ocw = tid & 127;
        const int oc0 = ocw*2;
        float u0 = mw0[576*256 + oc0],     u1 = mw0[576*256 + oc0 + 1];
        float v0 = mw0[577*256 + oc0],     v1 = mw0[577*256 + oc0 + 1];
        float b0v = b0eff[oc0],            b1v = b0eff[oc0 + 1];
        const __half2* G2 = (const __half2*)G;
        for (int m = (tid >> 7); m < SB; m += 2) {
            __half2 gg = G2[(size_t)p_s[m]*128 + ocw];
            float rh = relh_s[m], rw = relw_s[m];
            float x0v = fmaf(rh, u0, fmaf(rw, v0, __low2float(gg)  + b0v));
            float x1v = fmaf(rh, u1, fmaf(rw, v1, __high2float(gg) + b1v));
            __half2 hv = __floats2half2_rn(fmaxf(x0v, 0.f), fmaxf(x1v, 0.f));
            actu[m*(ASH/2) + ocw] = *(const uint32_t*)&hv;
        }
    }
    __syncthreads();

    const int m0  = (wid & 3)*32;
    const int n0b = (wid >> 2)*128;

    const __half* Ws[3] = {w1h, w2h, w3h};
    const float*  Bs[3] = {b1, b2, b3};

    int cnt = 0;
    for (int L = 0; L < 3; L++) {
        bias_s[tid] = Bs[L][tid];

        float acc[2][16][4];
#pragma unroll
        for (int mt = 0; mt < 2; mt++)
#pragma unroll
            for (int nt = 0; nt < 16; nt++)
#pragma unroll
                for (int i = 0; i < 4; i++) acc[mt][nt][i] = 0.f;

        for (int c = 0; c < 4; c++) {
            const bool has_next = (c < 3) || (L < 2);
            if (has_next) {
                const __half* Wn = (c < 3) ? Ws[L] : Ws[L+1];
                const int cn = (c < 3) ? c + 1 : 0;
                load_wchunk(wbaddr[(cnt + 1) & 1], Wn, cn, tid);
                cp_commit();
                cp_wait<1>();
            } else {
                cp_wait<0>();
            }
            __syncthreads();

            const uint32_t* wb = wbuf[cnt & 1];
#pragma unroll
            for (int ks = 0; ks < 4; ks++) {
                const int kw = c*32 + ks*8;
                uint32_t af[2][4];
#pragma unroll
                for (int mt = 0; mt < 2; mt++) {
                    const uint32_t* ar = actu + (m0 + mt*16 + g)*(ASH/2) + kw + t;
                    af[mt][0] = ar[0];
                    af[mt][2] = ar[4];
                    af[mt][1] = ar[8*(ASH/2)];
                    af[mt][3] = ar[8*(ASH/2) + 4];
                }
                const uint32_t* wp = wb + (size_t)(n0b + g)*(WSH/2) + ks*8 + t;
#pragma unroll
                for (int nt = 0; nt < 16; nt++) {
                    uint32_t b0 = wp[nt*8*(WSH/2)];
                    uint32_t b1r = wp[nt*8*(WSH/2) + 4];
                    mma16(acc[0][nt], af[0][0], af[0][1], af[0][2], af[0][3], b0, b1r);
                    mma16(acc[1][nt], af[1][0], af[1][1], af[1][2], af[1][3], b0, b1r);
                }
            }
            cnt++;
            __syncthreads();
        }

#pragma unroll
        for (int mt = 0; mt < 2; mt++) {
            const int r0 = m0 + mt*16 + g;
#pragma unroll
            for (int nt = 0; nt < 16; nt++) {
                const int col = n0b + nt*8 + 2*t;
                float v0 = fmaxf(acc[mt][nt][0] + bias_s[col],     0.f);
                float v1 = fmaxf(acc[mt][nt][1] + bias_s[col + 1], 0.f);
                float v2 = fmaxf(acc[mt][nt][2] + bias_s[col],     0.f);
                float v3 = fmaxf(acc[mt][nt][3] + bias_s[col + 1], 0.f);
                __half2 h01 = __floats2half2_rn(v0, v1);
                __half2 h23 = __floats2half2_rn(v2, v3);
                const int cw = (n0b >> 1) + nt*4 + t;
                actu[r0*(ASH/2) + cw]     = *(const uint32_t*)&h01;
                actu[(r0+8)*(ASH/2) + cw] = *(const uint32_t*)&h23;
            }
        }
        __syncthreads();
    }

    {
        float* wsm = (float*)(dyn + OFF_WB0);
        for (int i = tid; i < 768; i += QTHREADS) wsm[i] = w4[i];
        __syncthreads();
        if (tid < SB) {
            const __half* ap = acth + tid*ASH;
            float s0 = b4[0], s1 = b4[1], s2 = b4[2];
#pragma unroll 4
            for (int k = 0; k < 256; k++) {
                float a = __half2float(ap[k]);
                s0 = fmaf(a, wsm[k*3 + 0], s0);
                s1 = fmaf(a, wsm[k*3 + 1], s1);
                s2 = fmaf(a, wsm[k*3 + 2], s2);
            }
            pred_s[tid][0] = s0; pred_s[tid][1] = s1; pred_s[tid][2] = s2;
        }
    }
    __syncthreads();

    if (tid < QB) {
        int bb = tid*4;
        float a0 = area_s[bb+0], a1 = area_s[bb+1];
        float a2 = area_s[bb+2], a3 = area_s[bb+3];
        float tot = a0 + a1 + a2 + a3 + 1e-9f;
        int q = blockIdx.x*QB + tid;
#pragma unroll
        for (int j = 0; j < 3; j++) {
            float num = pred_s[bb+0][j]*a3 + pred_s[bb+1][j]*a2
                      + pred_s[bb+2][j]*a1 + pred_s[bb+3][j]*a0;
            float yv = num / tot;
            yv = fminf(fmaxf(yv, 0.f), 1.f);
            out[(size_t)j*NQ + q] = yv;
        }
    }
}

// ------------------------------ launch --------------------------------------
extern "C" void kernel_launch(void* const* d_in, const int* in_sizes, int n_in,
                              void* d_out, int out_size)
{
    const float* x      = (const float*)d_in[0];
    const float* head_w = (const float*)d_in[2];
    const float* head_b = (const float*)d_in[3];
    const float* rb_w   = (const float*)d_in[4];
    const float* rb_b   = (const float*)d_in[5];
    const float* tail_w = (const float*)d_in[6];
    const float* tail_b = (const float*)d_in[7];
    const float* mw0 = (const float*)d_in[8];
    const float* mb0 = (const float*)d_in[9];
    const float* mw1 = (const float*)d_in[10];
    const float* mb1 = (const float*)d_in[11];
    const float* mw2 = (const float*)d_in[12];
    const float* mb2 = (const float*)d_in[13];
    const float* mw3 = (const float*)d_in[14];
    const float* mb3 = (const float*)d_in[15];
    const float* mw4 = (const float*)d_in[16];
    const float* mb4 = (const float*)d_in[17];
    float* out = (float*)d_out;

    float *h0, *A, *C, *b0eff;
    __half *h0h, *Ah, *Bh, *Ch, *G, *w1h, *w2h, *w3h, *wch, *wl0;
    cudaGetSymbolAddress((void**)&h0, g_h0);
    cudaGetSymbolAddress((void**)&A,  g_A);
    cudaGetSymbolAddress((void**)&C,  g_C);
    cudaGetSymbolAddress((void**)&h0h, g_h0h);
    cudaGetSymbolAddress((void**)&Ah,  g_Ah);
    cudaGetSymbolAddress((void**)&Bh,  g_Bh);
    cudaGetSymbolAddress((void**)&Ch,  g_Ch);
    cudaGetSymbolAddress((void**)&G,  g_G);
    cudaGetSymbolAddress((void**)&b0eff, g_b0eff);
    cudaGetSymbolAddress((void**)&w1h, g_w1h);
    cudaGetSymbolAddress((void**)&w2h, g_w2h);
    cudaGetSymbolAddress((void**)&w3h, g_w3h);
    cudaGetSymbolAddress((void**)&wch, g_wch);
    cudaGetSymbolAddress((void**)&wl0, g_wl0);

    // weight transforms
    prep_wch<<<(33*36864)/256, 256>>>(rb_w, tail_w, wch);
    prep_wl0<<<(4*36864)/256, 256>>>(mw0, wl0);
    prep_kernel<<<1, 256>>>(mw0, mb0, b0eff);
    w_fp16_kernel<<<768, 256>>>(mw1, mw2, mw3, w1h, w2h, w3h);

    cudaFuncSetAttribute(conv_gemm<0>, cudaFuncAttributeMaxDynamicSharedMemorySize, GSMEM2);
    cudaFuncSetAttribute(conv_gemm<1>, cudaFuncAttributeMaxDynamicSharedMemorySize, GSMEM2);
    cudaFuncSetAttribute(conv_gemm<2>, cudaFuncAttributeMaxDynamicSharedMemorySize, GSMEM2);

    // head conv -> fp32 h0 + fp16 h0h
    conv_head<<<dim3(W/CTX, H/CTY, 4), dim3(CTX, CTY)>>>(x, head_w, head_b,
                                                         h0, h0h);

    // 16 resblocks (fp16 tensor, full-row CTAs)
    const __half* hcur_h = h0h;
    const float*  hcur_f = h0;
    float*  ppf[2] = {A, C};
    __half* pph[2] = {Ah, Ch};
    for (int i = 0; i < 16; i++) {
        conv_gemm<0><<<128, 256, GSMEM2>>>(hcur_h, wch + (size_t)(2*i)*36864,
                                           rb_b + 2*i*64, nullptr,
                                           nullptr, Bh);
        conv_gemm<1><<<128, 256, GSMEM2>>>(Bh, wch + (size_t)(2*i+1)*36864,
                                           rb_b + (2*i+1)*64, hcur_f,
                                           ppf[i & 1], pph[i & 1]);
        hcur_h = pph[i & 1];
        hcur_f = ppf[i & 1];
    }
    // tail conv + global residual -> feat (fp16 only) in Bh
    conv_gemm<1><<<128, 256, GSMEM2>>>(hcur_h, wch + (size_t)32*36864,
                                       tail_b, h0, nullptr, Bh);

    // layer-0-as-conv: G[16384][256] fp16
    conv_gemm<2><<<dim3(128, 1, 4), 256, GSMEM2>>>(Bh, wl0, nullptr, nullptr,
                                                   nullptr, G);

    cudaFuncSetAttribute(query_kernel,
                         cudaFuncAttributeMaxDynamicSharedMemorySize,
                         DYN_BYTES);
    query_kernel<<<NQ/QB, QTHREADS, DYN_BYTES>>>(
        G, mw0, b0eff, w1h, mb1, w2h, mb2, w3h, mb3, mw4, mb4, out);
}